// round 1
// baseline (speedup 1.0000x reference)
#include <cuda_runtime.h>
#include <cuda_bf16.h>
#include <math.h>

// Problem constants
#define BATCH 2
#define SEQ   2048
#define DMODEL 1024
#define NHEAD 16
#define HDIM  64
#define MROWS (BATCH*SEQ)          // 4096

// ---------------- scratch (no cudaMalloc allowed) ----------------
__device__ float g_qkv[MROWS * 3 * DMODEL];                 // (B*S, 3072)
__device__ float g_q[BATCH * NHEAD * SEQ * HDIM];
__device__ float g_k[BATCH * NHEAD * SEQ * HDIM];
__device__ float g_v[BATCH * NHEAD * SEQ * HDIM];
__device__ float g_att[MROWS * DMODEL];                     // (B*S, 1024)

// ---------------- GEMM: C[M,N] = A[M,K] @ B[N,K]^T + bias[N] ----------------
#define GBM 128
#define GBN 128
#define GBK 16
#define GTM 8
#define GTN 8
// 256 threads, each computes an 8x8 microtile.
__global__ void __launch_bounds__(256)
gemm_nt_bias(const float* __restrict__ A, const float* __restrict__ B,
             const float* __restrict__ bias, float* __restrict__ C,
             int M, int N, int K)
{
    __shared__ float As[GBM][GBK];      // stride 16, float4-storable
    __shared__ float Bs[GBN][GBK + 1];  // padded to break bank conflicts

    const int tid = threadIdx.x;
    const int tx = tid % (GBN / GTN);   // 0..15
    const int ty = tid / (GBN / GTN);   // 0..15
    const int m0 = blockIdx.y * GBM;
    const int n0 = blockIdx.x * GBN;

    // cooperative load mapping: 256 threads, float4 each, 2 rows-of-64 passes
    const int lr = tid / (GBK / 4);          // 0..63
    const int lc = (tid % (GBK / 4)) * 4;    // 0,4,8,12

    float acc[GTM][GTN];
#pragma unroll
    for (int i = 0; i < GTM; i++)
#pragma unroll
        for (int j = 0; j < GTN; j++) acc[i][j] = 0.f;

    for (int k0 = 0; k0 < K; k0 += GBK) {
#pragma unroll
        for (int h = 0; h < GBM; h += 64) {
            float4 va = *reinterpret_cast<const float4*>(&A[(size_t)(m0 + lr + h) * K + k0 + lc]);
            *reinterpret_cast<float4*>(&As[lr + h][lc]) = va;
        }
#pragma unroll
        for (int h = 0; h < GBN; h += 64) {
            float4 vb = *reinterpret_cast<const float4*>(&B[(size_t)(n0 + lr + h) * K + k0 + lc]);
            Bs[lr + h][lc + 0] = vb.x;
            Bs[lr + h][lc + 1] = vb.y;
            Bs[lr + h][lc + 2] = vb.z;
            Bs[lr + h][lc + 3] = vb.w;
        }
        __syncthreads();

#pragma unroll
        for (int k = 0; k < GBK; k++) {
            float a[GTM], b[GTN];
#pragma unroll
            for (int i = 0; i < GTM; i++) a[i] = As[ty * GTM + i][k];
#pragma unroll
            for (int j = 0; j < GTN; j++) b[j] = Bs[tx * GTN + j][k];
#pragma unroll
            for (int i = 0; i < GTM; i++)
#pragma unroll
                for (int j = 0; j < GTN; j++)
                    acc[i][j] += a[i] * b[j];
        }
        __syncthreads();
    }

#pragma unroll
    for (int i = 0; i < GTM; i++) {
        int m = m0 + ty * GTM + i;
#pragma unroll
        for (int j = 0; j < GTN; j++) {
            int n = n0 + tx * GTN + j;
            C[(size_t)m * N + n] = acc[i][j] + bias[n];
        }
    }
}

// ---------------- RoPE + split/transpose ----------------
// qkv: (B*S, 3072) -> q,k (rotated), v : (B, H, S, Dh)
__global__ void rope_split(const float* __restrict__ qkv,
                           float* __restrict__ q, float* __restrict__ k,
                           float* __restrict__ v)
{
    int idx = blockIdx.x * blockDim.x + threadIdx.x;   // over B*S*H*(Dh/2)
    const int TOT = BATCH * SEQ * NHEAD * (HDIM / 2);
    if (idx >= TOT) return;
    int i = idx % (HDIM / 2);            // pair index 0..31
    int h = (idx / (HDIM / 2)) % NHEAD;
    int s = (idx / (HDIM / 2 * NHEAD)) % SEQ;
    int b = idx / (HDIM / 2 * NHEAD * SEQ);

    const float* row = qkv + (size_t)(b * SEQ + s) * (3 * DMODEL);
    int d0 = h * HDIM + 2 * i;
    float q1 = row[d0],           q2 = row[d0 + 1];
    float k1 = row[DMODEL + d0],  k2 = row[DMODEL + d0 + 1];
    float v1 = row[2*DMODEL + d0],v2 = row[2*DMODEL + d0 + 1];

    // freqs[i] = 10000^(-2i/64); theta computed in fp32 like the reference,
    // trig evaluated in double for accuracy.
    float freq = (float)pow(10000.0, -(double)(2 * i) / (double)HDIM);
    float th = (float)s * freq;
    float c  = (float)cos((double)th);
    float sn = (float)sin((double)th);

    size_t o = ((size_t)((b * NHEAD + h) * SEQ + s)) * HDIM + 2 * i;
    q[o]     = q1 * c - q2 * sn;
    q[o + 1] = q1 * sn + q2 * c;
    k[o]     = k1 * c - k2 * sn;
    k[o + 1] = k1 * sn + k2 * c;
    v[o]     = v1;
    v[o + 1] = v2;
}

// ---------------- causal flash attention ----------------
// One thread per query row. Q and O accumulator in registers,
// K/V tiles in SMEM (broadcast reads).
#define ABM 128   // queries per block (= blockDim.x)
#define ABN 32    // kv tile
__global__ void __launch_bounds__(128)
attn_kernel(const float* __restrict__ Q, const float* __restrict__ Kg,
            const float* __restrict__ Vg, float* __restrict__ O)
{
    __shared__ float Ks[ABN][HDIM];
    __shared__ float Vs[ABN][HDIM];

    const int t = threadIdx.x;
    const int qblk = blockIdx.x;   // 0..15
    const int h = blockIdx.y;      // 0..15
    const int b = blockIdx.z;      // 0..1
    const int qi = qblk * ABM + t;

    const float* qrow = Q + ((size_t)((b * NHEAD + h) * SEQ + qi)) * HDIM;
    float q[HDIM];
#pragma unroll
    for (int d = 0; d < HDIM; d++) q[d] = __ldg(&qrow[d]);

    float o[HDIM];
#pragma unroll
    for (int d = 0; d < HDIM; d++) o[d] = 0.f;
    float m = -INFINITY, l = 0.f;

    const float* kb = Kg + ((size_t)(b * NHEAD + h) * SEQ) * HDIM;
    const float* vb = Vg + ((size_t)(b * NHEAD + h) * SEQ) * HDIM;
    const float scale = 0.125f;   // 1/sqrt(64)

    const int ntiles = qblk * (ABM / ABN) + (ABM / ABN);  // covers kv <= qblk*128+127

    for (int tile = 0; tile < ntiles; tile++) {
        const int n0 = tile * ABN;
        __syncthreads();   // protect previous tile's Ks/Vs
        // cooperative load: ABN*HDIM = 2048 floats per buffer, 128 thr * 4 float4
#pragma unroll
        for (int u = 0; u < 4; u++) {
            int e = (u * 128 + t) * 4;      // 0..2044 step 4
            int r = e >> 6, cd = e & 63;
            *reinterpret_cast<float4*>(&Ks[r][cd]) =
                *reinterpret_cast<const float4*>(&kb[(size_t)(n0 + r) * HDIM + cd]);
            *reinterpret_cast<float4*>(&Vs[r][cd]) =
                *reinterpret_cast<const float4*>(&vb[(size_t)(n0 + r) * HDIM + cd]);
        }
        __syncthreads();

        if (n0 > qi) continue;   // fully masked for this thread

        float sc[ABN];
        float tm = -INFINITY;
#pragma unroll
        for (int kk = 0; kk < ABN; kk++) {
            float s0 = 0.f, s1 = 0.f, s2 = 0.f, s3 = 0.f;
#pragma unroll
            for (int d = 0; d < HDIM; d += 4) {
                s0 += q[d + 0] * Ks[kk][d + 0];
                s1 += q[d + 1] * Ks[kk][d + 1];
                s2 += q[d + 2] * Ks[kk][d + 2];
                s3 += q[d + 3] * Ks[kk][d + 3];
            }
            float s = ((s0 + s1) + (s2 + s3)) * scale;
            if (n0 + kk > qi) s = -INFINITY;
            sc[kk] = s;
            tm = fmaxf(tm, s);
        }

        float mnew = fmaxf(m, tm);
        float corr = __expf(m - mnew);   // m=-inf first time -> 0
        l *= corr;
#pragma unroll
        for (int d = 0; d < HDIM; d++) o[d] *= corr;
        m = mnew;

#pragma unroll
        for (int kk = 0; kk < ABN; kk++) {
            float p = __expf(sc[kk] - m);   // masked -inf -> 0
            l += p;
#pragma unroll
            for (int d = 0; d < HDIM; d++)
                o[d] += p * Vs[kk][d];
        }
    }

    float inv = 1.f / l;
    float* orow = O + ((size_t)(b * SEQ + qi)) * DMODEL + h * HDIM;
#pragma unroll
    for (int d = 0; d < HDIM; d++) orow[d] = o[d] * inv;
}

// ---------------- launcher ----------------
extern "C" void kernel_launch(void* const* d_in, const int* in_sizes, int n_in,
                              void* d_out, int out_size)
{
    const float* x     = (const float*)d_in[0];   // (2,2048,1024)
    const float* w_qkv = (const float*)d_in[1];   // (3072,1024)
    const float* b_qkv = (const float*)d_in[2];   // (3072,)
    const float* w_out = (const float*)d_in[3];   // (1024,1024)
    const float* b_out = (const float*)d_in[4];   // (1024,)
    float* out = (float*)d_out;                   // (2,2048,1024)

    float *qkv, *q, *k, *v, *att;
    cudaGetSymbolAddress((void**)&qkv, g_qkv);
    cudaGetSymbolAddress((void**)&q,   g_q);
    cudaGetSymbolAddress((void**)&k,   g_k);
    cudaGetSymbolAddress((void**)&v,   g_v);
    cudaGetSymbolAddress((void**)&att, g_att);

    // 1) QKV projection: (4096,1024) @ (3072,1024)^T + b
    {
        dim3 grid(3 * DMODEL / GBN, MROWS / GBM);
        gemm_nt_bias<<<grid, 256>>>(x, w_qkv, b_qkv, qkv, MROWS, 3 * DMODEL, DMODEL);
    }
    // 2) RoPE + split to (B,H,S,Dh)
    {
        int tot = BATCH * SEQ * NHEAD * (HDIM / 2);
        rope_split<<<(tot + 255) / 256, 256>>>(qkv, q, k, v);
    }
    // 3) causal attention -> (B,S,D)
    {
        dim3 grid(SEQ / ABM, NHEAD, BATCH);
        attn_kernel<<<grid, ABM>>>(q, k, v, att);
    }
    // 4) output projection
    {
        dim3 grid(DMODEL / GBN, MROWS / GBM);
        gemm_nt_bias<<<grid, 256>>>(att, w_out, b_out, out, MROWS, DMODEL, DMODEL);
    }
}

// round 5
// speedup vs baseline: 1.2105x; 1.2105x over previous
#include <cuda_runtime.h>
#include <cuda_bf16.h>
#include <cstdint>
#include <math.h>

// Problem constants
#define BATCH 2
#define SEQ   2048
#define DMODEL 1024
#define NHEAD 16
#define HDIM  64
#define MROWS (BATCH*SEQ)          // 4096

// ---------------- scratch (no cudaMalloc allowed) ----------------
__device__ float g_qkv[MROWS * 3 * DMODEL];                 // (B*S, 3072)
__device__ float g_q[BATCH * NHEAD * SEQ * HDIM];
__device__ float g_k[BATCH * NHEAD * SEQ * HDIM];
__device__ float g_v[BATCH * NHEAD * SEQ * HDIM];
__device__ float g_att[MROWS * DMODEL];                     // (B*S, 1024)

// tf32 hi/lo split scratch
__device__ float g_xhi[MROWS * DMODEL],       g_xlo[MROWS * DMODEL];
__device__ float g_wqkvhi[3 * DMODEL * DMODEL], g_wqkvlo[3 * DMODEL * DMODEL];
__device__ float g_wouthi[DMODEL * DMODEL],   g_woutlo[DMODEL * DMODEL];
__device__ float g_atthi[MROWS * DMODEL],     g_attlo[MROWS * DMODEL];

// ================= helpers =================
__device__ __forceinline__ uint32_t smem_u32(const void* p) {
    uint32_t a;
    asm("{ .reg .u64 t; cvta.to.shared.u64 t, %1; cvt.u32.u64 %0, t; }" : "=r"(a) : "l"(p));
    return a;
}
__device__ __forceinline__ float tf32_rn(float x) {
    uint32_t u;
    asm("cvt.rna.tf32.f32 %0, %1;" : "=r"(u) : "f"(x));
    return __uint_as_float(u);
}
#define CP_ASYNC16(dst, src) \
    asm volatile("cp.async.cg.shared.global [%0], [%1], 16;" :: "r"(dst), "l"(src))
#define CP_COMMIT() asm volatile("cp.async.commit_group;" ::: "memory")
#define CP_WAIT0()  asm volatile("cp.async.wait_group 0;" ::: "memory")

__device__ __forceinline__ void mma_tf32(float* d, const uint32_t* a, const uint32_t* b) {
    asm volatile(
        "mma.sync.aligned.m16n8k8.row.col.f32.tf32.tf32.f32 "
        "{%0,%1,%2,%3}, {%4,%5,%6,%7}, {%8,%9}, {%0,%1,%2,%3};"
        : "+f"(d[0]), "+f"(d[1]), "+f"(d[2]), "+f"(d[3])
        : "r"(a[0]), "r"(a[1]), "r"(a[2]), "r"(a[3]), "r"(b[0]), "r"(b[1]));
}

// ---------------- split kernel: a -> (hi, lo) both tf32-exact ----------------
__global__ void split_tf32(const float* __restrict__ in,
                           float* __restrict__ hi, float* __restrict__ lo, int n4)
{
    int i = blockIdx.x * blockDim.x + threadIdx.x;
    if (i >= n4) return;
    float4 v = reinterpret_cast<const float4*>(in)[i];
    float4 h, l;
    h.x = tf32_rn(v.x); l.x = tf32_rn(v.x - h.x);
    h.y = tf32_rn(v.y); l.y = tf32_rn(v.y - h.y);
    h.z = tf32_rn(v.z); l.z = tf32_rn(v.z - h.z);
    h.w = tf32_rn(v.w); l.w = tf32_rn(v.w - h.w);
    reinterpret_cast<float4*>(hi)[i] = h;
    reinterpret_cast<float4*>(lo)[i] = l;
}

// ================ tf32x3 mma.sync GEMM ================
// C[M,N] = A[M,K] @ B[N,K]^T + bias
// CTA tile 128x128, 256 threads (8 warps as 4(m) x 2(n), warp tile 32x64).
// K chunk = 16, double-buffered smem via cp.async.
// Smem rows padded to 20 floats -> conflict-free fragment loads.
#define KC 16
#define ROWPAD 20
#define ARR_F (128 * ROWPAD)            // floats per array (2560)
#define BUF_F (4 * ARR_F)               // Ahi,Alo,Bhi,Blo (10240 floats)
#define GSMEM_B (2 * BUF_F * 4)         // 81920 bytes

__global__ void __launch_bounds__(256)
gemm_tf32x3(const float* __restrict__ Ahi, const float* __restrict__ Alo,
            const float* __restrict__ Bhi, const float* __restrict__ Blo,
            const float* __restrict__ bias, float* __restrict__ C,
            int M, int N, int K)
{
    extern __shared__ __align__(128) float smem[];
    const uint32_t smb = smem_u32(smem);

    const int tid  = threadIdx.x;
    const int wid  = tid >> 5;
    const int lane = tid & 31;
    const int warp_m = wid & 3;          // 0..3 -> 32 rows each
    const int warp_n = wid >> 2;         // 0..1 -> 64 cols each
    const int m0 = blockIdx.y * 128;
    const int n0 = blockIdx.x * 128;

    const float* gsrc[4] = { Ahi, Alo, Bhi, Blo };

    // per-thread cp.async mapping: 8 x float4; i>>1 selects array
    const int within = ((tid & 255) | 0);     // reused below per i

    float acc[2][8][4];
#pragma unroll
    for (int mt = 0; mt < 2; mt++)
#pragma unroll
        for (int nt = 0; nt < 8; nt++)
#pragma unroll
            for (int r = 0; r < 4; r++) acc[mt][nt][r] = 0.f;

    const int NCHUNK = K / KC;

    // ---- load chunk helper (manually unrolled by array) ----
    auto load_chunk = [&](int c, int buf) {
#pragma unroll
        for (int i = 0; i < 8; i++) {
            const int arr = i >> 1;                 // 0..3
            const int f4  = (i & 1) * 256 + tid;    // 0..511 within array
            const int row = f4 >> 2;                // 0..127
            const int seg = f4 & 3;                 // 0..3
            const int base = (arr < 2) ? m0 : n0;
            const float* src = gsrc[arr] + (size_t)(base + row) * K + c * KC + seg * 4;
            uint32_t dst = smb + (uint32_t)(buf * BUF_F + arr * ARR_F + row * ROWPAD + seg * 4) * 4;
            CP_ASYNC16(dst, src);
        }
    };

    load_chunk(0, 0);
    CP_COMMIT();

    for (int c = 0; c < NCHUNK; c++) {
        const int buf = c & 1;
        CP_WAIT0();
        __syncthreads();
        if (c + 1 < NCHUNK) { load_chunk(c + 1, buf ^ 1); CP_COMMIT(); }

        const float* sA_hi = smem + buf * BUF_F;
        const float* sA_lo = sA_hi + ARR_F;
        const float* sB_hi = sA_lo + ARR_F;
        const float* sB_lo = sB_hi + ARR_F;

#pragma unroll
        for (int ks = 0; ks < 2; ks++) {
            const int kb = ks * 8;
            // ---- load fragments ----
            uint32_t ah[2][4], al[2][4], bh[8][2], bl[8][2];
#pragma unroll
            for (int mt = 0; mt < 2; mt++) {
                int r = warp_m * 32 + mt * 16 + (lane >> 2);
                int cc = kb + (lane & 3);
                ah[mt][0] = __float_as_uint(sA_hi[r * ROWPAD + cc]);
                ah[mt][1] = __float_as_uint(sA_hi[(r + 8) * ROWPAD + cc]);
                ah[mt][2] = __float_as_uint(sA_hi[r * ROWPAD + cc + 4]);
                ah[mt][3] = __float_as_uint(sA_hi[(r + 8) * ROWPAD + cc + 4]);
                al[mt][0] = __float_as_uint(sA_lo[r * ROWPAD + cc]);
                al[mt][1] = __float_as_uint(sA_lo[(r + 8) * ROWPAD + cc]);
                al[mt][2] = __float_as_uint(sA_lo[r * ROWPAD + cc + 4]);
                al[mt][3] = __float_as_uint(sA_lo[(r + 8) * ROWPAD + cc + 4]);
            }
#pragma unroll
            for (int nt = 0; nt < 8; nt++) {
                int nn = warp_n * 64 + nt * 8 + (lane >> 2);
                int kk = kb + (lane & 3);
                bh[nt][0] = __float_as_uint(sB_hi[nn * ROWPAD + kk]);
                bh[nt][1] = __float_as_uint(sB_hi[nn * ROWPAD + kk + 4]);
                bl[nt][0] = __float_as_uint(sB_lo[nn * ROWPAD + kk]);
                bl[nt][1] = __float_as_uint(sB_lo[nn * ROWPAD + kk + 4]);
            }
            // ---- 3 passes, acc reuse distance 16 ----
#pragma unroll
            for (int nt = 0; nt < 8; nt++)
#pragma unroll
                for (int mt = 0; mt < 2; mt++)
                    mma_tf32(acc[mt][nt], ah[mt], bh[nt]);
#pragma unroll
            for (int nt = 0; nt < 8; nt++)
#pragma unroll
                for (int mt = 0; mt < 2; mt++)
                    mma_tf32(acc[mt][nt], al[mt], bh[nt]);
#pragma unroll
            for (int nt = 0; nt < 8; nt++)
#pragma unroll
                for (int mt = 0; mt < 2; mt++)
                    mma_tf32(acc[mt][nt], ah[mt], bl[nt]);
        }
    }
    (void)within;

    // ---- epilogue ----
#pragma unroll
    for (int mt = 0; mt < 2; mt++) {
        int r0 = m0 + warp_m * 32 + mt * 16 + (lane >> 2);
#pragma unroll
        for (int nt = 0; nt < 8; nt++) {
            int col = n0 + warp_n * 64 + nt * 8 + (lane & 3) * 2;
            float b0 = __ldg(&bias[col]);
            float b1 = __ldg(&bias[col + 1]);
            float2 v0 = { acc[mt][nt][0] + b0, acc[mt][nt][1] + b1 };
            float2 v1 = { acc[mt][nt][2] + b0, acc[mt][nt][3] + b1 };
            *reinterpret_cast<float2*>(&C[(size_t)r0 * N + col])       = v0;
            *reinterpret_cast<float2*>(&C[(size_t)(r0 + 8) * N + col]) = v1;
        }
    }
}

// ---------------- RoPE + split/transpose ----------------
__global__ void rope_split(const float* __restrict__ qkv,
                           float* __restrict__ q, float* __restrict__ k,
                           float* __restrict__ v)
{
    int idx = blockIdx.x * blockDim.x + threadIdx.x;
    const int TOT = BATCH * SEQ * NHEAD * (HDIM / 2);
    if (idx >= TOT) return;
    int i = idx % (HDIM / 2);
    int h = (idx / (HDIM / 2)) % NHEAD;
    int s = (idx / (HDIM / 2 * NHEAD)) % SEQ;
    int b = idx / (HDIM / 2 * NHEAD * SEQ);

    const float* row = qkv + (size_t)(b * SEQ + s) * (3 * DMODEL);
    int d0 = h * HDIM + 2 * i;
    float q1 = row[d0],            q2 = row[d0 + 1];
    float k1 = row[DMODEL + d0],   k2 = row[DMODEL + d0 + 1];
    float v1 = row[2*DMODEL + d0], v2 = row[2*DMODEL + d0 + 1];

    float freq = (float)pow(10000.0, -(double)(2 * i) / (double)HDIM);
    float th = (float)s * freq;
    float c  = (float)cos((double)th);
    float sn = (float)sin((double)th);

    size_t o = ((size_t)((b * NHEAD + h) * SEQ + s)) * HDIM + 2 * i;
    q[o]     = q1 * c - q2 * sn;
    q[o + 1] = q1 * sn + q2 * c;
    k[o]     = k1 * c - k2 * sn;
    k[o + 1] = k1 * sn + k2 * c;
    v[o]     = v1;
    v[o + 1] = v2;
}

// ---------------- causal flash attention (scalar fp32) ----------------
#define ABM 128
#define ABN 32
__global__ void __launch_bounds__(128)
attn_kernel(const float* __restrict__ Q, const float* __restrict__ Kg,
            const float* __restrict__ Vg, float* __restrict__ O)
{
    __shared__ float Ks[ABN][HDIM];
    __shared__ float Vs[ABN][HDIM];

    const int t = threadIdx.x;
    const int qblk = blockIdx.x;
    const int h = blockIdx.y;
    const int b = blockIdx.z;
    const int qi = qblk * ABM + t;

    const float* qrow = Q + ((size_t)((b * NHEAD + h) * SEQ + qi)) * HDIM;
    float q[HDIM];
#pragma unroll
    for (int d = 0; d < HDIM; d++) q[d] = __ldg(&qrow[d]);

    float o[HDIM];
#pragma unroll
    for (int d = 0; d < HDIM; d++) o[d] = 0.f;
    float m = -INFINITY, l = 0.f;

    const float* kb = Kg + ((size_t)(b * NHEAD + h) * SEQ) * HDIM;
    const float* vb = Vg + ((size_t)(b * NHEAD + h) * SEQ) * HDIM;
    const float scale = 0.125f;

    const int ntiles = qblk * (ABM / ABN) + (ABM / ABN);

    for (int tile = 0; tile < ntiles; tile++) {
        const int n0 = tile * ABN;
        __syncthreads();
#pragma unroll
        for (int u = 0; u < 4; u++) {
            int e = (u * 128 + t) * 4;
            int r = e >> 6, cd = e & 63;
            *reinterpret_cast<float4*>(&Ks[r][cd]) =
                *reinterpret_cast<const float4*>(&kb[(size_t)(n0 + r) * HDIM + cd]);
            *reinterpret_cast<float4*>(&Vs[r][cd]) =
                *reinterpret_cast<const float4*>(&vb[(size_t)(n0 + r) * HDIM + cd]);
        }
        __syncthreads();

        if (n0 > qi) continue;

        float sc[ABN];
        float tm = -INFINITY;
#pragma unroll
        for (int kk = 0; kk < ABN; kk++) {
            float s0 = 0.f, s1 = 0.f, s2 = 0.f, s3 = 0.f;
#pragma unroll
            for (int d = 0; d < HDIM; d += 4) {
                s0 += q[d + 0] * Ks[kk][d + 0];
                s1 += q[d + 1] * Ks[kk][d + 1];
                s2 += q[d + 2] * Ks[kk][d + 2];
                s3 += q[d + 3] * Ks[kk][d + 3];
            }
            float s = ((s0 + s1) + (s2 + s3)) * scale;
            if (n0 + kk > qi) s = -INFINITY;
            sc[kk] = s;
            tm = fmaxf(tm, s);
        }

        float mnew = fmaxf(m, tm);
        float corr = __expf(m - mnew);
        l *= corr;
#pragma unroll
        for (int d = 0; d < HDIM; d++) o[d] *= corr;
        m = mnew;

#pragma unroll
        for (int kk = 0; kk < ABN; kk++) {
            float p = __expf(sc[kk] - m);
            l += p;
#pragma unroll
            for (int d = 0; d < HDIM; d++)
                o[d] += p * Vs[kk][d];
        }
    }

    float inv = 1.f / l;
    float* orow = O + ((size_t)(b * SEQ + qi)) * DMODEL + h * HDIM;
#pragma unroll
    for (int d = 0; d < HDIM; d++) orow[d] = o[d] * inv;
}

// ---------------- launcher ----------------
extern "C" void kernel_launch(void* const* d_in, const int* in_sizes, int n_in,
                              void* d_out, int out_size)
{
    const float* x     = (const float*)d_in[0];
    const float* w_qkv = (const float*)d_in[1];
    const float* b_qkv = (const float*)d_in[2];
    const float* w_out = (const float*)d_in[3];
    const float* b_out = (const float*)d_in[4];
    float* out = (float*)d_out;

    float *qkv, *q, *k, *v, *att;
    float *xhi, *xlo, *wqh, *wql, *woh, *wol, *ath, *atl;
    cudaGetSymbolAddress((void**)&qkv, g_qkv);
    cudaGetSymbolAddress((void**)&q,   g_q);
    cudaGetSymbolAddress((void**)&k,   g_k);
    cudaGetSymbolAddress((void**)&v,   g_v);
    cudaGetSymbolAddress((void**)&att, g_att);
    cudaGetSymbolAddress((void**)&xhi, g_xhi);
    cudaGetSymbolAddress((void**)&xlo, g_xlo);
    cudaGetSymbolAddress((void**)&wqh, g_wqkvhi);
    cudaGetSymbolAddress((void**)&wql, g_wqkvlo);
    cudaGetSymbolAddress((void**)&woh, g_wouthi);
    cudaGetSymbolAddress((void**)&wol, g_woutlo);
    cudaGetSymbolAddress((void**)&ath, g_atthi);
    cudaGetSymbolAddress((void**)&atl, g_attlo);

    cudaFuncSetAttribute(gemm_tf32x3,
                         cudaFuncAttributeMaxDynamicSharedMemorySize, GSMEM_B);

    // 0) tf32 hi/lo splits of inputs and weights
    {
        int n4x = MROWS * DMODEL / 4;
        split_tf32<<<(n4x + 255) / 256, 256>>>(x, xhi, xlo, n4x);
        int n4q = 3 * DMODEL * DMODEL / 4;
        split_tf32<<<(n4q + 255) / 256, 256>>>(w_qkv, wqh, wql, n4q);
        int n4o = DMODEL * DMODEL / 4;
        split_tf32<<<(n4o + 255) / 256, 256>>>(w_out, woh, wol, n4o);
    }
    // 1) QKV projection: (4096,1024) @ (3072,1024)^T + b
    {
        dim3 grid(3 * DMODEL / 128, MROWS / 128);
        gemm_tf32x3<<<grid, 256, GSMEM_B>>>(xhi, xlo, wqh, wql, b_qkv, qkv,
                                            MROWS, 3 * DMODEL, DMODEL);
    }
    // 2) RoPE + split heads
    {
        int tot = BATCH * SEQ * NHEAD * (HDIM / 2);
        rope_split<<<(tot + 255) / 256, 256>>>(qkv, q, k, v);
    }
    // 3) causal attention
    {
        dim3 grid(SEQ / ABM, NHEAD, BATCH);
        attn_kernel<<<grid, ABM>>>(q, k, v, att);
    }
    // 4) split attention output, then output projection
    {
        int n4a = MROWS * DMODEL / 4;
        split_tf32<<<(n4a + 255) / 256, 256>>>(att, ath, atl, n4a);
        dim3 grid(DMODEL / 128, MROWS / 128);
        gemm_tf32x3<<<grid, 256, GSMEM_B>>>(ath, atl, woh, wol, b_out, out,
                                            MROWS, DMODEL, DMODEL);
    }
}

// round 6
// speedup vs baseline: 1.6672x; 1.3773x over previous
#include <cuda_runtime.h>
#include <cuda_bf16.h>
#include <cstdint>
#include <math.h>

// Problem constants
#define BATCH 2
#define SEQ   2048
#define DMODEL 1024
#define NHEAD 16
#define HDIM  64
#define MROWS (BATCH*SEQ)          // 4096

// ---------------- scratch (no cudaMalloc allowed) ----------------
__device__ float g_qkv[MROWS * 3 * DMODEL];                 // (B*S, 3072)
__device__ float g_att[MROWS * DMODEL];                     // (B*S, 1024)

// tf32 hi/lo split scratch for GEMMs
__device__ float g_xhi[MROWS * DMODEL],         g_xlo[MROWS * DMODEL];
__device__ float g_wqkvhi[3 * DMODEL * DMODEL], g_wqkvlo[3 * DMODEL * DMODEL];
__device__ float g_wouthi[DMODEL * DMODEL],     g_woutlo[DMODEL * DMODEL];
__device__ float g_atthi[MROWS * DMODEL],       g_attlo[MROWS * DMODEL];

// attention operands, pre-split tf32 hi/lo
#define HELEMS (BATCH * NHEAD * SEQ * HDIM)
__device__ float g_qhi[HELEMS], g_qlo[HELEMS];   // (b,h,s,d)
__device__ float g_khi[HELEMS], g_klo[HELEMS];   // (b,h,s,d)
__device__ float g_vthi[HELEMS], g_vtlo[HELEMS]; // (b,h,d,s)  V transposed

// ================= helpers =================
__device__ __forceinline__ uint32_t smem_u32(const void* p) {
    uint32_t a;
    asm("{ .reg .u64 t; cvta.to.shared.u64 t, %1; cvt.u32.u64 %0, t; }" : "=r"(a) : "l"(p));
    return a;
}
__device__ __forceinline__ float tf32_rn(float x) {
    uint32_t u;
    asm("cvt.rna.tf32.f32 %0, %1;" : "=r"(u) : "f"(x));
    return __uint_as_float(u);
}
#define CP_ASYNC16(dst, src) \
    asm volatile("cp.async.cg.shared.global [%0], [%1], 16;" :: "r"(dst), "l"(src))
#define CP_COMMIT() asm volatile("cp.async.commit_group;" ::: "memory")
#define CP_WAIT0()  asm volatile("cp.async.wait_group 0;" ::: "memory")

__device__ __forceinline__ void mma_tf32(float* d, const uint32_t* a, const uint32_t* b) {
    asm volatile(
        "mma.sync.aligned.m16n8k8.row.col.f32.tf32.tf32.f32 "
        "{%0,%1,%2,%3}, {%4,%5,%6,%7}, {%8,%9}, {%0,%1,%2,%3};"
        : "+f"(d[0]), "+f"(d[1]), "+f"(d[2]), "+f"(d[3])
        : "r"(a[0]), "r"(a[1]), "r"(a[2]), "r"(a[3]), "r"(b[0]), "r"(b[1]));
}

// ---------------- split kernel: a -> (hi, lo) both tf32-exact ----------------
__global__ void split_tf32(const float* __restrict__ in,
                           float* __restrict__ hi, float* __restrict__ lo, int n4)
{
    int i = blockIdx.x * blockDim.x + threadIdx.x;
    if (i >= n4) return;
    float4 v = reinterpret_cast<const float4*>(in)[i];
    float4 h, l;
    h.x = tf32_rn(v.x); l.x = tf32_rn(v.x - h.x);
    h.y = tf32_rn(v.y); l.y = tf32_rn(v.y - h.y);
    h.z = tf32_rn(v.z); l.z = tf32_rn(v.z - h.z);
    h.w = tf32_rn(v.w); l.w = tf32_rn(v.w - h.w);
    reinterpret_cast<float4*>(hi)[i] = h;
    reinterpret_cast<float4*>(lo)[i] = l;
}

// ================ tf32x3 mma.sync GEMM (unchanged from R5) ================
#define KC 16
#define ROWPAD 20
#define ARR_F (128 * ROWPAD)
#define BUF_F (4 * ARR_F)
#define GSMEM_B (2 * BUF_F * 4)

__global__ void __launch_bounds__(256)
gemm_tf32x3(const float* __restrict__ Ahi, const float* __restrict__ Alo,
            const float* __restrict__ Bhi, const float* __restrict__ Blo,
            const float* __restrict__ bias, float* __restrict__ C,
            int M, int N, int K)
{
    extern __shared__ __align__(128) float smem[];
    const uint32_t smb = smem_u32(smem);

    const int tid  = threadIdx.x;
    const int wid  = tid >> 5;
    const int lane = tid & 31;
    const int warp_m = wid & 3;
    const int warp_n = wid >> 2;
    const int m0 = blockIdx.y * 128;
    const int n0 = blockIdx.x * 128;

    const float* gsrc[4] = { Ahi, Alo, Bhi, Blo };

    float acc[2][8][4];
#pragma unroll
    for (int mt = 0; mt < 2; mt++)
#pragma unroll
        for (int nt = 0; nt < 8; nt++)
#pragma unroll
            for (int r = 0; r < 4; r++) acc[mt][nt][r] = 0.f;

    const int NCHUNK = K / KC;

    auto load_chunk = [&](int c, int buf) {
#pragma unroll
        for (int i = 0; i < 8; i++) {
            const int arr = i >> 1;
            const int f4  = (i & 1) * 256 + tid;
            const int row = f4 >> 2;
            const int seg = f4 & 3;
            const int base = (arr < 2) ? m0 : n0;
            const float* src = gsrc[arr] + (size_t)(base + row) * K + c * KC + seg * 4;
            uint32_t dst = smb + (uint32_t)(buf * BUF_F + arr * ARR_F + row * ROWPAD + seg * 4) * 4;
            CP_ASYNC16(dst, src);
        }
    };

    load_chunk(0, 0);
    CP_COMMIT();

    for (int c = 0; c < NCHUNK; c++) {
        const int buf = c & 1;
        CP_WAIT0();
        __syncthreads();
        if (c + 1 < NCHUNK) { load_chunk(c + 1, buf ^ 1); CP_COMMIT(); }

        const float* sA_hi = smem + buf * BUF_F;
        const float* sA_lo = sA_hi + ARR_F;
        const float* sB_hi = sA_lo + ARR_F;
        const float* sB_lo = sB_hi + ARR_F;

#pragma unroll
        for (int ks = 0; ks < 2; ks++) {
            const int kb = ks * 8;
            uint32_t ah[2][4], al[2][4], bh[8][2], bl[8][2];
#pragma unroll
            for (int mt = 0; mt < 2; mt++) {
                int r = warp_m * 32 + mt * 16 + (lane >> 2);
                int cc = kb + (lane & 3);
                ah[mt][0] = __float_as_uint(sA_hi[r * ROWPAD + cc]);
                ah[mt][1] = __float_as_uint(sA_hi[(r + 8) * ROWPAD + cc]);
                ah[mt][2] = __float_as_uint(sA_hi[r * ROWPAD + cc + 4]);
                ah[mt][3] = __float_as_uint(sA_hi[(r + 8) * ROWPAD + cc + 4]);
                al[mt][0] = __float_as_uint(sA_lo[r * ROWPAD + cc]);
                al[mt][1] = __float_as_uint(sA_lo[(r + 8) * ROWPAD + cc]);
                al[mt][2] = __float_as_uint(sA_lo[r * ROWPAD + cc + 4]);
                al[mt][3] = __float_as_uint(sA_lo[(r + 8) * ROWPAD + cc + 4]);
            }
#pragma unroll
            for (int nt = 0; nt < 8; nt++) {
                int nn = warp_n * 64 + nt * 8 + (lane >> 2);
                int kk = kb + (lane & 3);
                bh[nt][0] = __float_as_uint(sB_hi[nn * ROWPAD + kk]);
                bh[nt][1] = __float_as_uint(sB_hi[nn * ROWPAD + kk + 4]);
                bl[nt][0] = __float_as_uint(sB_lo[nn * ROWPAD + kk]);
                bl[nt][1] = __float_as_uint(sB_lo[nn * ROWPAD + kk + 4]);
            }
#pragma unroll
            for (int nt = 0; nt < 8; nt++)
#pragma unroll
                for (int mt = 0; mt < 2; mt++)
                    mma_tf32(acc[mt][nt], ah[mt], bh[nt]);
#pragma unroll
            for (int nt = 0; nt < 8; nt++)
#pragma unroll
                for (int mt = 0; mt < 2; mt++)
                    mma_tf32(acc[mt][nt], al[mt], bh[nt]);
#pragma unroll
            for (int nt = 0; nt < 8; nt++)
#pragma unroll
                for (int mt = 0; mt < 2; mt++)
                    mma_tf32(acc[mt][nt], ah[mt], bl[nt]);
        }
    }

#pragma unroll
    for (int mt = 0; mt < 2; mt++) {
        int r0 = m0 + warp_m * 32 + mt * 16 + (lane >> 2);
#pragma unroll
        for (int nt = 0; nt < 8; nt++) {
            int col = n0 + warp_n * 64 + nt * 8 + (lane & 3) * 2;
            float b0 = __ldg(&bias[col]);
            float b1 = __ldg(&bias[col + 1]);
            float2 v0 = { acc[mt][nt][0] + b0, acc[mt][nt][1] + b1 };
            float2 v1 = { acc[mt][nt][2] + b0, acc[mt][nt][3] + b1 };
            *reinterpret_cast<float2*>(&C[(size_t)r0 * N + col])       = v0;
            *reinterpret_cast<float2*>(&C[(size_t)(r0 + 8) * N + col]) = v1;
        }
    }
}

// ---------------- RoPE + split heads + tf32 hi/lo split + V transpose ----------------
__global__ void rope_split2(const float* __restrict__ qkv,
                            float* __restrict__ qhi, float* __restrict__ qlo,
                            float* __restrict__ khi, float* __restrict__ klo,
                            float* __restrict__ vthi, float* __restrict__ vtlo)
{
    int idx = blockIdx.x * blockDim.x + threadIdx.x;
    const int TOT = BATCH * SEQ * NHEAD * (HDIM / 2);
    if (idx >= TOT) return;
    int i = idx % (HDIM / 2);
    int h = (idx / (HDIM / 2)) % NHEAD;
    int s = (idx / (HDIM / 2 * NHEAD)) % SEQ;
    int b = idx / (HDIM / 2 * NHEAD * SEQ);

    const float* row = qkv + (size_t)(b * SEQ + s) * (3 * DMODEL);
    int d0 = h * HDIM + 2 * i;
    float q1 = row[d0],            q2 = row[d0 + 1];
    float k1 = row[DMODEL + d0],   k2 = row[DMODEL + d0 + 1];
    float v1 = row[2*DMODEL + d0], v2 = row[2*DMODEL + d0 + 1];

    float freq = (float)pow(10000.0, -(double)(2 * i) / (double)HDIM);
    float th = (float)s * freq;
    float c  = (float)cos((double)th);
    float sn = (float)sin((double)th);

    float qa = q1 * c - q2 * sn;
    float qb = q1 * sn + q2 * c;
    float ka = k1 * c - k2 * sn;
    float kb = k1 * sn + k2 * c;

    size_t oq = ((size_t)((b * NHEAD + h) * SEQ + s)) * HDIM + 2 * i;
    float hh;
    hh = tf32_rn(qa); qhi[oq]     = hh; qlo[oq]     = tf32_rn(qa - hh);
    hh = tf32_rn(qb); qhi[oq + 1] = hh; qlo[oq + 1] = tf32_rn(qb - hh);
    hh = tf32_rn(ka); khi[oq]     = hh; klo[oq]     = tf32_rn(ka - hh);
    hh = tf32_rn(kb); khi[oq + 1] = hh; klo[oq + 1] = tf32_rn(kb - hh);

    size_t ov = ((size_t)((b * NHEAD + h) * HDIM + 2 * i)) * SEQ + s;
    hh = tf32_rn(v1); vthi[ov]       = hh; vtlo[ov]       = tf32_rn(v1 - hh);
    hh = tf32_rn(v2); vthi[ov + SEQ] = hh; vtlo[ov + SEQ] = tf32_rn(v2 - hh);
}

// ---------------- tensor-core causal flash attention (tf32x3) ----------------
// Br=128, Bc=64, 8 warps; warp w owns query rows [16w, 16w+16).
// Smem: Kh,Kl,Vth,Vtl tiles [64][72] with permuted columns so that each
// m16n8k8 B-fragment (b0,b1) is a single conflict-free LDS.64.
#define ABC 64
#define ASTR 72
#define AARR (ABC * ASTR)            // 4608 floats
#define ASMEM_B (4 * AARR * 4)       // 73728 bytes

__global__ void __launch_bounds__(256)
attn_mma(const float* __restrict__ Qh, const float* __restrict__ Ql,
         const float* __restrict__ Kh, const float* __restrict__ Kl,
         const float* __restrict__ Vh, const float* __restrict__ Vl,
         float* __restrict__ Og)
{
    extern __shared__ __align__(128) float sm[];

    const int tid  = threadIdx.x;
    const int w    = tid >> 5;
    const int lane = tid & 31;
    const int g    = lane >> 2;      // row within 8
    const int q    = lane & 3;

    const int qblk = gridDim.x - 1 - blockIdx.x;   // heavy CTAs first
    const int h    = blockIdx.y;
    const int b    = blockIdx.z;
    const int qbase = qblk * 128 + 16 * w;

    const size_t headQK = (size_t)(b * NHEAD + h) * SEQ * HDIM;
    const size_t headV  = (size_t)(b * NHEAD + h) * HDIM * SEQ;

    // ---- Q fragments (persistent in registers) ----
    uint32_t aQh[8][4], aQl[8][4];
    {
        const float* qh = Qh + headQK;
        const float* ql = Ql + headQK;
        const int r0 = qbase + g;
#pragma unroll
        for (int kk = 0; kk < 8; kk++) {
            int c0 = kk * 8 + q;
            aQh[kk][0] = __float_as_uint(__ldg(&qh[(size_t)r0 * 64 + c0]));
            aQh[kk][1] = __float_as_uint(__ldg(&qh[(size_t)(r0 + 8) * 64 + c0]));
            aQh[kk][2] = __float_as_uint(__ldg(&qh[(size_t)r0 * 64 + c0 + 4]));
            aQh[kk][3] = __float_as_uint(__ldg(&qh[(size_t)(r0 + 8) * 64 + c0 + 4]));
            aQl[kk][0] = __float_as_uint(__ldg(&ql[(size_t)r0 * 64 + c0]));
            aQl[kk][1] = __float_as_uint(__ldg(&ql[(size_t)(r0 + 8) * 64 + c0]));
            aQl[kk][2] = __float_as_uint(__ldg(&ql[(size_t)r0 * 64 + c0 + 4]));
            aQl[kk][3] = __float_as_uint(__ldg(&ql[(size_t)(r0 + 8) * 64 + c0 + 4]));
        }
    }

    float o[8][4];
#pragma unroll
    for (int j = 0; j < 8; j++)
#pragma unroll
        for (int e = 0; e < 4; e++) o[j][e] = 0.f;
    float mrow0 = -INFINITY, mrow1 = -INFINITY;
    float lrow0 = 0.f, lrow1 = 0.f;

    const float sscale = 0.125f * 1.44269504088896340736f;  // /sqrt(64) * log2(e)
    const int ntiles = 2 * (qblk + 1);

    float* sKh = sm;
    float* sKl = sm + AARR;
    float* sVh = sm + 2 * AARR;
    float* sVl = sm + 3 * AARR;

    for (int t = 0; t < ntiles; t++) {
        const int n0 = t * ABC;
        __syncthreads();
        // ---- cooperative tile load with column permutation ----
        {
            const float* srcs[4];
            int rstr[4];
            srcs[0] = Kh + headQK + (size_t)n0 * 64;  rstr[0] = 64;
            srcs[1] = Kl + headQK + (size_t)n0 * 64;  rstr[1] = 64;
            srcs[2] = Vh + headV + n0;                rstr[2] = SEQ;
            srcs[3] = Vl + headV + n0;                rstr[3] = SEQ;
#pragma unroll
            for (int arr = 0; arr < 4; arr++) {
                float* dst = sm + arr * AARR;
#pragma unroll
                for (int i = 0; i < 4; i++) {
                    int idx = i * 256 + tid;           // 0..1023
                    int row = idx >> 4;
                    int c4  = (idx & 15) * 4;
                    float4 v = *reinterpret_cast<const float4*>(
                        srcs[arr] + (size_t)row * rstr[arr] + c4);
                    float* drow = dst + row * ASTR;
                    const float* pv = reinterpret_cast<const float*>(&v);
#pragma unroll
                    for (int kq = 0; kq < 4; kq++) {
                        int col = c4 + kq;
                        int pcol = (col & ~7) | ((col & 3) << 1) | ((col >> 2) & 1);
                        drow[pcol] = pv[kq];
                    }
                }
            }
        }
        __syncthreads();

        if (n0 > qbase + 15) continue;     // fully masked for this warp

        // ---- S = Q K^T (tf32x3) ----
        float acc[8][4];
#pragma unroll
        for (int j = 0; j < 8; j++)
#pragma unroll
            for (int e = 0; e < 4; e++) acc[j][e] = 0.f;

#pragma unroll
        for (int kk = 0; kk < 8; kk++) {
#pragma unroll
            for (int j = 0; j < 8; j++) {
                float2 bh = *reinterpret_cast<const float2*>(
                    &sKh[(8 * j + g) * ASTR + kk * 8 + q * 2]);
                float2 bl = *reinterpret_cast<const float2*>(
                    &sKl[(8 * j + g) * ASTR + kk * 8 + q * 2]);
                uint32_t ubh[2] = { __float_as_uint(bh.x), __float_as_uint(bh.y) };
                uint32_t ubl[2] = { __float_as_uint(bl.x), __float_as_uint(bl.y) };
                mma_tf32(acc[j], aQh[kk], ubh);
                mma_tf32(acc[j], aQl[kk], ubh);
                mma_tf32(acc[j], aQh[kk], ubl);
            }
        }

        // ---- softmax (log2 domain) ----
        const bool needmask = (n0 + 63 > qbase);
        float tmax0 = -INFINITY, tmax1 = -INFINITY;
#pragma unroll
        for (int j = 0; j < 8; j++) {
#pragma unroll
            for (int e = 0; e < 4; e++) {
                float s = acc[j][e] * sscale;
                if (needmask) {
                    int col = n0 + 8 * j + 2 * q + (e & 1);
                    int row = qbase + g + ((e >> 1) << 3);
                    if (col > row) s = -INFINITY;
                }
                acc[j][e] = s;
                if (e < 2) tmax0 = fmaxf(tmax0, s);
                else       tmax1 = fmaxf(tmax1, s);
            }
        }
        tmax0 = fmaxf(tmax0, __shfl_xor_sync(0xffffffffu, tmax0, 1));
        tmax0 = fmaxf(tmax0, __shfl_xor_sync(0xffffffffu, tmax0, 2));
        tmax1 = fmaxf(tmax1, __shfl_xor_sync(0xffffffffu, tmax1, 1));
        tmax1 = fmaxf(tmax1, __shfl_xor_sync(0xffffffffu, tmax1, 2));

        float mn0 = fmaxf(mrow0, tmax0);
        float mn1 = fmaxf(mrow1, tmax1);
        float corr0 = exp2f(mrow0 - mn0);
        float corr1 = exp2f(mrow1 - mn1);

        float sum0 = 0.f, sum1 = 0.f;
#pragma unroll
        for (int j = 0; j < 8; j++) {
            float p0 = exp2f(acc[j][0] - mn0);
            float p1 = exp2f(acc[j][1] - mn0);
            float p2 = exp2f(acc[j][2] - mn1);
            float p3 = exp2f(acc[j][3] - mn1);
            acc[j][0] = p0; acc[j][1] = p1; acc[j][2] = p2; acc[j][3] = p3;
            sum0 += p0 + p1;
            sum1 += p2 + p3;
        }
        sum0 += __shfl_xor_sync(0xffffffffu, sum0, 1);
        sum0 += __shfl_xor_sync(0xffffffffu, sum0, 2);
        sum1 += __shfl_xor_sync(0xffffffffu, sum1, 1);
        sum1 += __shfl_xor_sync(0xffffffffu, sum1, 2);

        lrow0 = lrow0 * corr0 + sum0;
        lrow1 = lrow1 * corr1 + sum1;
        mrow0 = mn0;
        mrow1 = mn1;

#pragma unroll
        for (int j = 0; j < 8; j++) {
            o[j][0] *= corr0; o[j][1] *= corr0;
            o[j][2] *= corr1; o[j][3] *= corr1;
        }

        // ---- O += P V (tf32x3); P transposed to A-frag layout via shuffles ----
        const int srcA = (lane & ~3) | (q >> 1);
        const int srcB = srcA + 2;
        const bool odd = (q & 1);
#pragma unroll
        for (int kk = 0; kk < 8; kk++) {
            float x0 = __shfl_sync(0xffffffffu, acc[kk][0], srcA);
            float x1 = __shfl_sync(0xffffffffu, acc[kk][1], srcA);
            float x2 = __shfl_sync(0xffffffffu, acc[kk][2], srcA);
            float x3 = __shfl_sync(0xffffffffu, acc[kk][3], srcA);
            float y0 = __shfl_sync(0xffffffffu, acc[kk][0], srcB);
            float y1 = __shfl_sync(0xffffffffu, acc[kk][1], srcB);
            float y2 = __shfl_sync(0xffffffffu, acc[kk][2], srcB);
            float y3 = __shfl_sync(0xffffffffu, acc[kk][3], srcB);
            float a0 = odd ? x1 : x0;   // P[row   ][8kk+q]
            float a1 = odd ? x3 : x2;   // P[row+8 ][8kk+q]
            float a2 = odd ? y1 : y0;   // P[row   ][8kk+q+4]
            float a3 = odd ? y3 : y2;   // P[row+8 ][8kk+q+4]

            float h0 = tf32_rn(a0), l0 = tf32_rn(a0 - h0);
            float h1 = tf32_rn(a1), l1 = tf32_rn(a1 - h1);
            float h2 = tf32_rn(a2), l2 = tf32_rn(a2 - h2);
            float h3 = tf32_rn(a3), l3 = tf32_rn(a3 - h3);
            uint32_t uph[4] = { __float_as_uint(h0), __float_as_uint(h1),
                                __float_as_uint(h2), __float_as_uint(h3) };
            uint32_t upl[4] = { __float_as_uint(l0), __float_as_uint(l1),
                                __float_as_uint(l2), __float_as_uint(l3) };
#pragma unroll
            for (int j2 = 0; j2 < 8; j2++) {
                float2 vh = *reinterpret_cast<const float2*>(
                    &sVh[(8 * j2 + g) * ASTR + kk * 8 + q * 2]);
                float2 vl = *reinterpret_cast<const float2*>(
                    &sVl[(8 * j2 + g) * ASTR + kk * 8 + q * 2]);
                uint32_t uvh[2] = { __float_as_uint(vh.x), __float_as_uint(vh.y) };
                uint32_t uvl[2] = { __float_as_uint(vl.x), __float_as_uint(vl.y) };
                mma_tf32(o[j2], uph, uvh);
                mma_tf32(o[j2], upl, uvh);
                mma_tf32(o[j2], uph, uvl);
            }
        }
    }

    // ---- epilogue ----
    float inv0 = 1.f / lrow0;
    float inv1 = 1.f / lrow1;
    float* ob = Og + ((size_t)(b * SEQ + qbase + g)) * DMODEL + h * HDIM;
#pragma unroll
    for (int j2 = 0; j2 < 8; j2++) {
        int d0 = 8 * j2 + 2 * q;
        float2 v0 = { o[j2][0] * inv0, o[j2][1] * inv0 };
        float2 v1 = { o[j2][2] * inv1, o[j2][3] * inv1 };
        *reinterpret_cast<float2*>(&ob[d0]) = v0;
        *reinterpret_cast<float2*>(&ob[(size_t)8 * DMODEL + d0]) = v1;
    }
}

// ---------------- launcher ----------------
extern "C" void kernel_launch(void* const* d_in, const int* in_sizes, int n_in,
                              void* d_out, int out_size)
{
    const float* x     = (const float*)d_in[0];
    const float* w_qkv = (const float*)d_in[1];
    const float* b_qkv = (const float*)d_in[2];
    const float* w_out = (const float*)d_in[3];
    const float* b_out = (const float*)d_in[4];
    float* out = (float*)d_out;

    float *qkv, *att;
    float *xhi, *xlo, *wqh, *wql, *woh, *wol, *ath, *atl;
    float *qhi, *qlo, *khi, *klo, *vth, *vtl;
    cudaGetSymbolAddress((void**)&qkv, g_qkv);
    cudaGetSymbolAddress((void**)&att, g_att);
    cudaGetSymbolAddress((void**)&xhi, g_xhi);
    cudaGetSymbolAddress((void**)&xlo, g_xlo);
    cudaGetSymbolAddress((void**)&wqh, g_wqkvhi);
    cudaGetSymbolAddress((void**)&wql, g_wqkvlo);
    cudaGetSymbolAddress((void**)&woh, g_wouthi);
    cudaGetSymbolAddress((void**)&wol, g_woutlo);
    cudaGetSymbolAddress((void**)&ath, g_atthi);
    cudaGetSymbolAddress((void**)&atl, g_attlo);
    cudaGetSymbolAddress((void**)&qhi, g_qhi);
    cudaGetSymbolAddress((void**)&qlo, g_qlo);
    cudaGetSymbolAddress((void**)&khi, g_khi);
    cudaGetSymbolAddress((void**)&klo, g_klo);
    cudaGetSymbolAddress((void**)&vth, g_vthi);
    cudaGetSymbolAddress((void**)&vtl, g_vtlo);

    cudaFuncSetAttribute(gemm_tf32x3,
                         cudaFuncAttributeMaxDynamicSharedMemorySize, GSMEM_B);
    cudaFuncSetAttribute(attn_mma,
                         cudaFuncAttributeMaxDynamicSharedMemorySize, ASMEM_B);

    // 0) tf32 hi/lo splits of inputs and weights
    {
        int n4x = MROWS * DMODEL / 4;
        split_tf32<<<(n4x + 255) / 256, 256>>>(x, xhi, xlo, n4x);
        int n4q = 3 * DMODEL * DMODEL / 4;
        split_tf32<<<(n4q + 255) / 256, 256>>>(w_qkv, wqh, wql, n4q);
        int n4o = DMODEL * DMODEL / 4;
        split_tf32<<<(n4o + 255) / 256, 256>>>(w_out, woh, wol, n4o);
    }
    // 1) QKV projection
    {
        dim3 grid(3 * DMODEL / 128, MROWS / 128);
        gemm_tf32x3<<<grid, 256, GSMEM_B>>>(xhi, xlo, wqh, wql, b_qkv, qkv,
                                            MROWS, 3 * DMODEL, DMODEL);
    }
    // 2) RoPE + head split + tf32 split + V transpose
    {
        int tot = BATCH * SEQ * NHEAD * (HDIM / 2);
        rope_split2<<<(tot + 255) / 256, 256>>>(qkv, qhi, qlo, khi, klo, vth, vtl);
    }
    // 3) tensor-core causal attention
    {
        dim3 grid(SEQ / 128, NHEAD, BATCH);
        attn_mma<<<grid, 256, ASMEM_B>>>(qhi, qlo, khi, klo, vth, vtl, att);
    }
    // 4) split attention output, then output projection
    {
        int n4a = MROWS * DMODEL / 4;
        split_tf32<<<(n4a + 255) / 256, 256>>>(att, ath, atl, n4a);
        dim3 grid(DMODEL / 128, MROWS / 128);
        gemm_tf32x3<<<grid, 256, GSMEM_B>>>(ath, atl, woh, wol, b_out, out,
                                            MROWS, DMODEL, DMODEL);
    }
}

// round 7
// speedup vs baseline: 1.8355x; 1.1009x over previous
#include <cuda_runtime.h>
#include <cuda_bf16.h>
#include <cstdint>
#include <math.h>

// Problem constants
#define BATCH 2
#define SEQ   2048
#define DMODEL 1024
#define NHEAD 16
#define HDIM  64
#define MROWS (BATCH*SEQ)          // 4096

// ---------------- scratch (no cudaMalloc allowed) ----------------
__device__ float g_qkv[MROWS * 3 * DMODEL];                 // (B*S, 3072)
__device__ float g_att[MROWS * DMODEL];                     // (B*S, 1024)

// tf32 hi/lo split scratch for GEMMs
__device__ float g_xhi[MROWS * DMODEL],         g_xlo[MROWS * DMODEL];
__device__ float g_wqkvhi[3 * DMODEL * DMODEL], g_wqkvlo[3 * DMODEL * DMODEL];
__device__ float g_wouthi[DMODEL * DMODEL],     g_woutlo[DMODEL * DMODEL];
__device__ float g_atthi[MROWS * DMODEL],       g_attlo[MROWS * DMODEL];

// attention operands, pre-split tf32 hi/lo
#define HELEMS (BATCH * NHEAD * SEQ * HDIM)
__device__ float g_qhi[HELEMS], g_qlo[HELEMS];   // (b,h,s,d) normal layout
__device__ float g_khi[HELEMS], g_klo[HELEMS];   // (b,h,s,d) d-cols PERMUTED within 8
__device__ float g_vthi[HELEMS];                 // (b,h,d,s) s-cols PERMUTED within 8

// ================= helpers =================
__device__ __forceinline__ uint32_t smem_u32(const void* p) {
    uint32_t a;
    asm("{ .reg .u64 t; cvta.to.shared.u64 t, %1; cvt.u32.u64 %0, t; }" : "=r"(a) : "l"(p));
    return a;
}
__device__ __forceinline__ float tf32_rn(float x) {
    uint32_t u;
    asm("cvt.rna.tf32.f32 %0, %1;" : "=r"(u) : "f"(x));
    return __uint_as_float(u);
}
__device__ __forceinline__ float ex2(float x) {
    float y;
    asm("ex2.approx.f32 %0, %1;" : "=f"(y) : "f"(x));
    return y;
}
__device__ __forceinline__ int perm8(int c) {
    return (c & ~7) | ((c & 3) << 1) | ((c >> 2) & 1);
}
#define CP_ASYNC16(dst, src) \
    asm volatile("cp.async.cg.shared.global [%0], [%1], 16;" :: "r"(dst), "l"(src))
#define CP_COMMIT() asm volatile("cp.async.commit_group;" ::: "memory")
#define CP_WAIT0()  asm volatile("cp.async.wait_group 0;" ::: "memory")
#define CP_WAIT1()  asm volatile("cp.async.wait_group 1;" ::: "memory")

__device__ __forceinline__ void mma_tf32(float* d, const uint32_t* a, const uint32_t* b) {
    asm volatile(
        "mma.sync.aligned.m16n8k8.row.col.f32.tf32.tf32.f32 "
        "{%0,%1,%2,%3}, {%4,%5,%6,%7}, {%8,%9}, {%0,%1,%2,%3};"
        : "+f"(d[0]), "+f"(d[1]), "+f"(d[2]), "+f"(d[3])
        : "r"(a[0]), "r"(a[1]), "r"(a[2]), "r"(a[3]), "r"(b[0]), "r"(b[1]));
}

// ---------------- split kernel: a -> (hi, lo) both tf32-exact ----------------
__global__ void split_tf32(const float* __restrict__ in,
                           float* __restrict__ hi, float* __restrict__ lo, int n4)
{
    int i = blockIdx.x * blockDim.x + threadIdx.x;
    if (i >= n4) return;
    float4 v = reinterpret_cast<const float4*>(in)[i];
    float4 h, l;
    h.x = tf32_rn(v.x); l.x = tf32_rn(v.x - h.x);
    h.y = tf32_rn(v.y); l.y = tf32_rn(v.y - h.y);
    h.z = tf32_rn(v.z); l.z = tf32_rn(v.z - h.z);
    h.w = tf32_rn(v.w); l.w = tf32_rn(v.w - h.w);
    reinterpret_cast<float4*>(hi)[i] = h;
    reinterpret_cast<float4*>(lo)[i] = l;
}

// ================ tf32x3 mma.sync GEMM (unchanged from R5) ================
#define KC 16
#define ROWPAD 20
#define ARR_F (128 * ROWPAD)
#define BUF_F (4 * ARR_F)
#define GSMEM_B (2 * BUF_F * 4)

__global__ void __launch_bounds__(256)
gemm_tf32x3(const float* __restrict__ Ahi, const float* __restrict__ Alo,
            const float* __restrict__ Bhi, const float* __restrict__ Blo,
            const float* __restrict__ bias, float* __restrict__ C,
            int M, int N, int K)
{
    extern __shared__ __align__(128) float smem[];
    const uint32_t smb = smem_u32(smem);

    const int tid  = threadIdx.x;
    const int wid  = tid >> 5;
    const int lane = tid & 31;
    const int warp_m = wid & 3;
    const int warp_n = wid >> 2;
    const int m0 = blockIdx.y * 128;
    const int n0 = blockIdx.x * 128;

    const float* gsrc[4] = { Ahi, Alo, Bhi, Blo };

    float acc[2][8][4];
#pragma unroll
    for (int mt = 0; mt < 2; mt++)
#pragma unroll
        for (int nt = 0; nt < 8; nt++)
#pragma unroll
            for (int r = 0; r < 4; r++) acc[mt][nt][r] = 0.f;

    const int NCHUNK = K / KC;

    auto load_chunk = [&](int c, int buf) {
#pragma unroll
        for (int i = 0; i < 8; i++) {
            const int arr = i >> 1;
            const int f4  = (i & 1) * 256 + tid;
            const int row = f4 >> 2;
            const int seg = f4 & 3;
            const int base = (arr < 2) ? m0 : n0;
            const float* src = gsrc[arr] + (size_t)(base + row) * K + c * KC + seg * 4;
            uint32_t dst = smb + (uint32_t)(buf * BUF_F + arr * ARR_F + row * ROWPAD + seg * 4) * 4;
            CP_ASYNC16(dst, src);
        }
    };

    load_chunk(0, 0);
    CP_COMMIT();

    for (int c = 0; c < NCHUNK; c++) {
        const int buf = c & 1;
        CP_WAIT0();
        __syncthreads();
        if (c + 1 < NCHUNK) { load_chunk(c + 1, buf ^ 1); CP_COMMIT(); }

        const float* sA_hi = smem + buf * BUF_F;
        const float* sA_lo = sA_hi + ARR_F;
        const float* sB_hi = sA_lo + ARR_F;
        const float* sB_lo = sB_hi + ARR_F;

#pragma unroll
        for (int ks = 0; ks < 2; ks++) {
            const int kb = ks * 8;
            uint32_t ah[2][4], al[2][4], bh[8][2], bl[8][2];
#pragma unroll
            for (int mt = 0; mt < 2; mt++) {
                int r = warp_m * 32 + mt * 16 + (lane >> 2);
                int cc = kb + (lane & 3);
                ah[mt][0] = __float_as_uint(sA_hi[r * ROWPAD + cc]);
                ah[mt][1] = __float_as_uint(sA_hi[(r + 8) * ROWPAD + cc]);
                ah[mt][2] = __float_as_uint(sA_hi[r * ROWPAD + cc + 4]);
                ah[mt][3] = __float_as_uint(sA_hi[(r + 8) * ROWPAD + cc + 4]);
                al[mt][0] = __float_as_uint(sA_lo[r * ROWPAD + cc]);
                al[mt][1] = __float_as_uint(sA_lo[(r + 8) * ROWPAD + cc]);
                al[mt][2] = __float_as_uint(sA_lo[r * ROWPAD + cc + 4]);
                al[mt][3] = __float_as_uint(sA_lo[(r + 8) * ROWPAD + cc + 4]);
            }
#pragma unroll
            for (int nt = 0; nt < 8; nt++) {
                int nn = warp_n * 64 + nt * 8 + (lane >> 2);
                int kk = kb + (lane & 3);
                bh[nt][0] = __float_as_uint(sB_hi[nn * ROWPAD + kk]);
                bh[nt][1] = __float_as_uint(sB_hi[nn * ROWPAD + kk + 4]);
                bl[nt][0] = __float_as_uint(sB_lo[nn * ROWPAD + kk]);
                bl[nt][1] = __float_as_uint(sB_lo[nn * ROWPAD + kk + 4]);
            }
#pragma unroll
            for (int nt = 0; nt < 8; nt++)
#pragma unroll
                for (int mt = 0; mt < 2; mt++)
                    mma_tf32(acc[mt][nt], ah[mt], bh[nt]);
#pragma unroll
            for (int nt = 0; nt < 8; nt++)
#pragma unroll
                for (int mt = 0; mt < 2; mt++)
                    mma_tf32(acc[mt][nt], al[mt], bh[nt]);
#pragma unroll
            for (int nt = 0; nt < 8; nt++)
#pragma unroll
                for (int mt = 0; mt < 2; mt++)
                    mma_tf32(acc[mt][nt], ah[mt], bl[nt]);
        }
    }

#pragma unroll
    for (int mt = 0; mt < 2; mt++) {
        int r0 = m0 + warp_m * 32 + mt * 16 + (lane >> 2);
#pragma unroll
        for (int nt = 0; nt < 8; nt++) {
            int col = n0 + warp_n * 64 + nt * 8 + (lane & 3) * 2;
            float b0 = __ldg(&bias[col]);
            float b1 = __ldg(&bias[col + 1]);
            float2 v0 = { acc[mt][nt][0] + b0, acc[mt][nt][1] + b1 };
            float2 v1 = { acc[mt][nt][2] + b0, acc[mt][nt][3] + b1 };
            *reinterpret_cast<float2*>(&C[(size_t)r0 * N + col])       = v0;
            *reinterpret_cast<float2*>(&C[(size_t)(r0 + 8) * N + col]) = v1;
        }
    }
}

// ---------------- RoPE + split heads + tf32 split (+ permuted K/V layouts) ----------------
__global__ void rope_split2(const float* __restrict__ qkv,
                            float* __restrict__ qhi, float* __restrict__ qlo,
                            float* __restrict__ khi, float* __restrict__ klo,
                            float* __restrict__ vthi)
{
    int idx = blockIdx.x * blockDim.x + threadIdx.x;
    const int TOT = BATCH * SEQ * NHEAD * (HDIM / 2);
    if (idx >= TOT) return;
    int i = idx % (HDIM / 2);
    int h = (idx / (HDIM / 2)) % NHEAD;
    int s = (idx / (HDIM / 2 * NHEAD)) % SEQ;
    int b = idx / (HDIM / 2 * NHEAD * SEQ);

    const float* row = qkv + (size_t)(b * SEQ + s) * (3 * DMODEL);
    int d0 = h * HDIM + 2 * i;
    float q1 = row[d0],            q2 = row[d0 + 1];
    float k1 = row[DMODEL + d0],   k2 = row[DMODEL + d0 + 1];
    float v1 = row[2*DMODEL + d0], v2 = row[2*DMODEL + d0 + 1];

    float freq = (float)pow(10000.0, -(double)(2 * i) / (double)HDIM);
    float th = (float)s * freq;
    float c  = (float)cos((double)th);
    float sn = (float)sin((double)th);

    float qa = q1 * c - q2 * sn;
    float qb = q1 * sn + q2 * c;
    float ka = k1 * c - k2 * sn;
    float kb = k1 * sn + k2 * c;

    size_t rowQ = ((size_t)((b * NHEAD + h) * SEQ + s)) * HDIM;
    float hh;
    // Q: normal layout
    hh = tf32_rn(qa); qhi[rowQ + 2*i]     = hh; qlo[rowQ + 2*i]     = tf32_rn(qa - hh);
    hh = tf32_rn(qb); qhi[rowQ + 2*i + 1] = hh; qlo[rowQ + 2*i + 1] = tf32_rn(qb - hh);
    // K: d-columns permuted within groups of 8
    int pc0 = perm8(2 * i), pc1 = perm8(2 * i + 1);
    hh = tf32_rn(ka); khi[rowQ + pc0] = hh; klo[rowQ + pc0] = tf32_rn(ka - hh);
    hh = tf32_rn(kb); khi[rowQ + pc1] = hh; klo[rowQ + pc1] = tf32_rn(kb - hh);
    // V^T: (b,h,d,s), s-columns permuted within groups of 8, tf32-rounded (hi only)
    int ps = perm8(s & 7) | (s & ~7);
    size_t ov = ((size_t)((b * NHEAD + h) * HDIM + 2 * i)) * SEQ + ps;
    vthi[ov]       = tf32_rn(v1);
    vthi[ov + SEQ] = tf32_rn(v2);
}

// ---------------- tensor-core causal flash attention (cp.async pipelined) ----------------
// Br=128, Bc=64, 8 warps; warp w owns query rows [16w, 16w+16).
// Smem per stage: Kh,Kl [64][72], Vh^T [64][72]; 2 stages, cp.async double buffer.
// Global K/V layouts are pre-permuted so LDS.64 fragment reads are conflict-free.
#define ABC 64
#define ASTR 72
#define AARR (ABC * ASTR)            // 4608 floats
#define ASTAGE (3 * AARR)            // 13824 floats
#define ASMEM_B (2 * ASTAGE * 4)     // 110592 bytes

__global__ void __launch_bounds__(256)
attn_mma(const float* __restrict__ Qh, const float* __restrict__ Ql,
         const float* __restrict__ Kh, const float* __restrict__ Kl,
         const float* __restrict__ Vh, float* __restrict__ Og)
{
    extern __shared__ __align__(128) float sm[];
    const uint32_t smb = smem_u32(sm);

    const int tid  = threadIdx.x;
    const int w    = tid >> 5;
    const int lane = tid & 31;
    const int g    = lane >> 2;      // row within 8
    const int q    = lane & 3;

    const int qblk = gridDim.x - 1 - blockIdx.x;   // heavy CTAs first
    const int h    = blockIdx.y;
    const int b    = blockIdx.z;
    const int qbase = qblk * 128 + 16 * w;

    const size_t headQK = (size_t)(b * NHEAD + h) * SEQ * HDIM;
    const size_t headV  = (size_t)(b * NHEAD + h) * HDIM * SEQ;

    // ---- Q fragments (persistent in registers) ----
    uint32_t aQh[8][4], aQl[8][4];
    {
        const float* qh = Qh + headQK;
        const float* ql = Ql + headQK;
        const int r0 = qbase + g;
#pragma unroll
        for (int kk = 0; kk < 8; kk++) {
            int c0 = kk * 8 + q;
            aQh[kk][0] = __float_as_uint(__ldg(&qh[(size_t)r0 * 64 + c0]));
            aQh[kk][1] = __float_as_uint(__ldg(&qh[(size_t)(r0 + 8) * 64 + c0]));
            aQh[kk][2] = __float_as_uint(__ldg(&qh[(size_t)r0 * 64 + c0 + 4]));
            aQh[kk][3] = __float_as_uint(__ldg(&qh[(size_t)(r0 + 8) * 64 + c0 + 4]));
            aQl[kk][0] = __float_as_uint(__ldg(&ql[(size_t)r0 * 64 + c0]));
            aQl[kk][1] = __float_as_uint(__ldg(&ql[(size_t)(r0 + 8) * 64 + c0]));
            aQl[kk][2] = __float_as_uint(__ldg(&ql[(size_t)r0 * 64 + c0 + 4]));
            aQl[kk][3] = __float_as_uint(__ldg(&ql[(size_t)(r0 + 8) * 64 + c0 + 4]));
        }
    }

    float o[8][4];
#pragma unroll
    for (int j = 0; j < 8; j++)
#pragma unroll
        for (int e = 0; e < 4; e++) o[j][e] = 0.f;
    float mrow0 = -INFINITY, mrow1 = -INFINITY;
    float lrow0 = 0.f, lrow1 = 0.f;

    const float sscale = 0.125f * 1.44269504088896340736f;  // /sqrt(64) * log2(e)
    const int ntiles = 2 * (qblk + 1);

    auto load_tile = [&](int t, int stg) {
        const int n0t = t * ABC;
        const float* srcs[3];
        srcs[0] = Kh + headQK + (size_t)n0t * 64;
        srcs[1] = Kl + headQK + (size_t)n0t * 64;
        srcs[2] = Vh + headV + n0t;
        const int rstr[3] = { 64, 64, SEQ };
#pragma unroll
        for (int arr = 0; arr < 3; arr++) {
#pragma unroll
            for (int i = 0; i < 4; i++) {
                int idx = i * 256 + tid;           // 0..1023
                int row = idx >> 4;
                int c4  = (idx & 15) * 4;
                uint32_t dst = smb +
                    (uint32_t)(stg * ASTAGE + arr * AARR + row * ASTR + c4) * 4;
                CP_ASYNC16(dst, srcs[arr] + (size_t)row * rstr[arr] + c4);
            }
        }
    };

    load_tile(0, 0);
    CP_COMMIT();

    for (int t = 0; t < ntiles; t++) {
        const int stg = t & 1;
        const int n0 = t * ABC;

        if (t + 1 < ntiles) {
            load_tile(t + 1, stg ^ 1);
            CP_COMMIT();
            CP_WAIT1();          // tile t resident; t+1 in flight
        } else {
            CP_WAIT0();
        }
        __syncthreads();

        if (n0 <= qbase + 15) {
            const float* sKh = sm + stg * ASTAGE;
            const float* sKl = sKh + AARR;
            const float* sVh = sKl + AARR;

            // ---- S = Q K^T (tf32x3) ----
            float acc[8][4];
#pragma unroll
            for (int j = 0; j < 8; j++)
#pragma unroll
                for (int e = 0; e < 4; e++) acc[j][e] = 0.f;

#pragma unroll
            for (int kk = 0; kk < 8; kk++) {
#pragma unroll
                for (int j = 0; j < 8; j++) {
                    float2 bh = *reinterpret_cast<const float2*>(
                        &sKh[(8 * j + g) * ASTR + kk * 8 + q * 2]);
                    float2 bl = *reinterpret_cast<const float2*>(
                        &sKl[(8 * j + g) * ASTR + kk * 8 + q * 2]);
                    uint32_t ubh[2] = { __float_as_uint(bh.x), __float_as_uint(bh.y) };
                    uint32_t ubl[2] = { __float_as_uint(bl.x), __float_as_uint(bl.y) };
                    mma_tf32(acc[j], aQh[kk], ubh);
                    mma_tf32(acc[j], aQl[kk], ubh);
                    mma_tf32(acc[j], aQh[kk], ubl);
                }
            }

            // ---- softmax (log2 domain) ----
            const bool needmask = (n0 + 63 > qbase);
            float tmax0 = -INFINITY, tmax1 = -INFINITY;
#pragma unroll
            for (int j = 0; j < 8; j++) {
#pragma unroll
                for (int e = 0; e < 4; e++) {
                    float s = acc[j][e] * sscale;
                    if (needmask) {
                        int col = n0 + 8 * j + 2 * q + (e & 1);
                        int rw  = qbase + g + ((e >> 1) << 3);
                        if (col > rw) s = -INFINITY;
                    }
                    acc[j][e] = s;
                    if (e < 2) tmax0 = fmaxf(tmax0, s);
                    else       tmax1 = fmaxf(tmax1, s);
                }
            }
            tmax0 = fmaxf(tmax0, __shfl_xor_sync(0xffffffffu, tmax0, 1));
            tmax0 = fmaxf(tmax0, __shfl_xor_sync(0xffffffffu, tmax0, 2));
            tmax1 = fmaxf(tmax1, __shfl_xor_sync(0xffffffffu, tmax1, 1));
            tmax1 = fmaxf(tmax1, __shfl_xor_sync(0xffffffffu, tmax1, 2));

            float mn0 = fmaxf(mrow0, tmax0);
            float mn1 = fmaxf(mrow1, tmax1);
            float corr0 = ex2(mrow0 - mn0);
            float corr1 = ex2(mrow1 - mn1);

            float sum0 = 0.f, sum1 = 0.f;
#pragma unroll
            for (int j = 0; j < 8; j++) {
                float p0 = ex2(acc[j][0] - mn0);
                float p1 = ex2(acc[j][1] - mn0);
                float p2 = ex2(acc[j][2] - mn1);
                float p3 = ex2(acc[j][3] - mn1);
                acc[j][0] = p0; acc[j][1] = p1; acc[j][2] = p2; acc[j][3] = p3;
                sum0 += p0 + p1;
                sum1 += p2 + p3;
            }
            sum0 += __shfl_xor_sync(0xffffffffu, sum0, 1);
            sum0 += __shfl_xor_sync(0xffffffffu, sum0, 2);
            sum1 += __shfl_xor_sync(0xffffffffu, sum1, 1);
            sum1 += __shfl_xor_sync(0xffffffffu, sum1, 2);

            lrow0 = lrow0 * corr0 + sum0;
            lrow1 = lrow1 * corr1 + sum1;
            mrow0 = mn0;
            mrow1 = mn1;

#pragma unroll
            for (int j = 0; j < 8; j++) {
                o[j][0] *= corr0; o[j][1] *= corr0;
                o[j][2] *= corr1; o[j][3] *= corr1;
            }

            // ---- O += P V (P split hi/lo; V tf32-rounded) ----
            const int srcA = (lane & ~3) | (q >> 1);
            const int srcB = srcA + 2;
            const bool odd = (q & 1);
#pragma unroll
            for (int kk = 0; kk < 8; kk++) {
                float x0 = __shfl_sync(0xffffffffu, acc[kk][0], srcA);
                float x1 = __shfl_sync(0xffffffffu, acc[kk][1], srcA);
                float x2 = __shfl_sync(0xffffffffu, acc[kk][2], srcA);
                float x3 = __shfl_sync(0xffffffffu, acc[kk][3], srcA);
                float y0 = __shfl_sync(0xffffffffu, acc[kk][0], srcB);
                float y1 = __shfl_sync(0xffffffffu, acc[kk][1], srcB);
                float y2 = __shfl_sync(0xffffffffu, acc[kk][2], srcB);
                float y3 = __shfl_sync(0xffffffffu, acc[kk][3], srcB);
                float a0 = odd ? x1 : x0;   // P[row   ][8kk+q]
                float a1 = odd ? x3 : x2;   // P[row+8 ][8kk+q]
                float a2 = odd ? y1 : y0;   // P[row   ][8kk+q+4]
                float a3 = odd ? y3 : y2;   // P[row+8 ][8kk+q+4]

                float h0 = tf32_rn(a0), l0 = tf32_rn(a0 - h0);
                float h1 = tf32_rn(a1), l1 = tf32_rn(a1 - h1);
                float h2 = tf32_rn(a2), l2 = tf32_rn(a2 - h2);
                float h3 = tf32_rn(a3), l3 = tf32_rn(a3 - h3);
                uint32_t uph[4] = { __float_as_uint(h0), __float_as_uint(h1),
                                    __float_as_uint(h2), __float_as_uint(h3) };
                uint32_t upl[4] = { __float_as_uint(l0), __float_as_uint(l1),
                                    __float_as_uint(l2), __float_as_uint(l3) };
#pragma unroll
                for (int j2 = 0; j2 < 8; j2++) {
                    float2 vh = *reinterpret_cast<const float2*>(
                        &sVh[(8 * j2 + g) * ASTR + kk * 8 + q * 2]);
                    uint32_t uvh[2] = { __float_as_uint(vh.x), __float_as_uint(vh.y) };
                    mma_tf32(o[j2], uph, uvh);
                    mma_tf32(o[j2], upl, uvh);
                }
            }
        }
        __syncthreads();
    }

    // ---- epilogue ----
    float inv0 = 1.f / lrow0;
    float inv1 = 1.f / lrow1;
    float* ob = Og + ((size_t)(b * SEQ + qbase + g)) * DMODEL + h * HDIM;
#pragma unroll
    for (int j2 = 0; j2 < 8; j2++) {
        int d0 = 8 * j2 + 2 * q;
        float2 v0 = { o[j2][0] * inv0, o[j2][1] * inv0 };
        float2 v1 = { o[j2][2] * inv1, o[j2][3] * inv1 };
        *reinterpret_cast<float2*>(&ob[d0]) = v0;
        *reinterpret_cast<float2*>(&ob[(size_t)8 * DMODEL + d0]) = v1;
    }
}

// ---------------- launcher ----------------
extern "C" void kernel_launch(void* const* d_in, const int* in_sizes, int n_in,
                              void* d_out, int out_size)
{
    const float* x     = (const float*)d_in[0];
    const float* w_qkv = (const float*)d_in[1];
    const float* b_qkv = (const float*)d_in[2];
    const float* w_out = (const float*)d_in[3];
    const float* b_out = (const float*)d_in[4];
    float* out = (float*)d_out;

    float *qkv, *att;
    float *xhi, *xlo, *wqh, *wql, *woh, *wol, *ath, *atl;
    float *qhi, *qlo, *khi, *klo, *vth;
    cudaGetSymbolAddress((void**)&qkv, g_qkv);
    cudaGetSymbolAddress((void**)&att, g_att);
    cudaGetSymbolAddress((void**)&xhi, g_xhi);
    cudaGetSymbolAddress((void**)&xlo, g_xlo);
    cudaGetSymbolAddress((void**)&wqh, g_wqkvhi);
    cudaGetSymbolAddress((void**)&wql, g_wqkvlo);
    cudaGetSymbolAddress((void**)&woh, g_wouthi);
    cudaGetSymbolAddress((void**)&wol, g_woutlo);
    cudaGetSymbolAddress((void**)&ath, g_atthi);
    cudaGetSymbolAddress((void**)&atl, g_attlo);
    cudaGetSymbolAddress((void**)&qhi, g_qhi);
    cudaGetSymbolAddress((void**)&qlo, g_qlo);
    cudaGetSymbolAddress((void**)&khi, g_khi);
    cudaGetSymbolAddress((void**)&klo, g_klo);
    cudaGetSymbolAddress((void**)&vth, g_vthi);

    cudaFuncSetAttribute(gemm_tf32x3,
                         cudaFuncAttributeMaxDynamicSharedMemorySize, GSMEM_B);
    cudaFuncSetAttribute(attn_mma,
                         cudaFuncAttributeMaxDynamicSharedMemorySize, ASMEM_B);

    // 0) tf32 hi/lo splits of inputs and weights
    {
        int n4x = MROWS * DMODEL / 4;
        split_tf32<<<(n4x + 255) / 256, 256>>>(x, xhi, xlo, n4x);
        int n4q = 3 * DMODEL * DMODEL / 4;
        split_tf32<<<(n4q + 255) / 256, 256>>>(w_qkv, wqh, wql, n4q);
        int n4o = DMODEL * DMODEL / 4;
        split_tf32<<<(n4o + 255) / 256, 256>>>(w_out, woh, wol, n4o);
    }
    // 1) QKV projection
    {
        dim3 grid(3 * DMODEL / 128, MROWS / 128);
        gemm_tf32x3<<<grid, 256, GSMEM_B>>>(xhi, xlo, wqh, wql, b_qkv, qkv,
                                            MROWS, 3 * DMODEL, DMODEL);
    }
    // 2) RoPE + head split + tf32 split + permuted K / V^T layouts
    {
        int tot = BATCH * SEQ * NHEAD * (HDIM / 2);
        rope_split2<<<(tot + 255) / 256, 256>>>(qkv, qhi, qlo, khi, klo, vth);
    }
    // 3) tensor-core causal attention
    {
        dim3 grid(SEQ / 128, NHEAD, BATCH);
        attn_mma<<<grid, 256, ASMEM_B>>>(qhi, qlo, khi, klo, vth, att);
    }
    // 4) split attention output, then output projection
    {
        int n4a = MROWS * DMODEL / 4;
        split_tf32<<<(n4a + 255) / 256, 256>>>(att, ath, atl, n4a);
        dim3 grid(DMODEL / 128, MROWS / 128);
        gemm_tf32x3<<<grid, 256, GSMEM_B>>>(ath, atl, woh, wol, b_out, out,
                                            MROWS, DMODEL, DMODEL);
    }
}

// round 8
// speedup vs baseline: 1.9230x; 1.0477x over previous
#include <cuda_runtime.h>
#include <cuda_bf16.h>
#include <cstdint>
#include <math.h>

// Problem constants
#define BATCH 2
#define SEQ   2048
#define DMODEL 1024
#define NHEAD 16
#define HDIM  64
#define MROWS (BATCH*SEQ)          // 4096

// ---------------- scratch (no cudaMalloc allowed) ----------------
__device__ float g_qkv[MROWS * 3 * DMODEL];                 // (B*S, 3072)
__device__ float g_att[MROWS * DMODEL];                     // (B*S, 1024)

// attention operands (tf32-domain), perm8'd for conflict-free LDS.64 frags
#define HELEMS (BATCH * NHEAD * SEQ * HDIM)
__device__ float g_qhi[HELEMS], g_qlo[HELEMS];   // (b,h,s,d) d-cols perm8'd
__device__ float g_khi[HELEMS];                  // (b,h,s,d) d-cols perm8'd
__device__ float g_vthi[HELEMS];                 // (b,h,d,s) s-cols perm8'd

// ================= helpers =================
__device__ __forceinline__ uint32_t smem_u32(const void* p) {
    uint32_t a;
    asm("{ .reg .u64 t; cvta.to.shared.u64 t, %1; cvt.u32.u64 %0, t; }" : "=r"(a) : "l"(p));
    return a;
}
__device__ __forceinline__ float tf32_rn(float x) {
    uint32_t u;
    asm("cvt.rna.tf32.f32 %0, %1;" : "=r"(u) : "f"(x));
    return __uint_as_float(u);
}
__device__ __forceinline__ float ex2(float x) {
    float y;
    asm("ex2.approx.f32 %0, %1;" : "=f"(y) : "f"(x));
    return y;
}
__device__ __forceinline__ int perm8(int c) {
    return (c & ~7) | ((c & 3) << 1) | ((c >> 2) & 1);
}
#define CP_ASYNC16(dst, src) \
    asm volatile("cp.async.cg.shared.global [%0], [%1], 16;" :: "r"(dst), "l"(src))
#define CP_COMMIT() asm volatile("cp.async.commit_group;" ::: "memory")
#define CP_WAIT0()  asm volatile("cp.async.wait_group 0;" ::: "memory")
#define CP_WAIT1()  asm volatile("cp.async.wait_group 1;" ::: "memory")

__device__ __forceinline__ void mma_tf32(float* d, const uint32_t* a, const uint32_t* b) {
    asm volatile(
        "mma.sync.aligned.m16n8k8.row.col.f32.tf32.tf32.f32 "
        "{%0,%1,%2,%3}, {%4,%5,%6,%7}, {%8,%9}, {%0,%1,%2,%3};"
        : "+f"(d[0]), "+f"(d[1]), "+f"(d[2]), "+f"(d[3])
        : "r"(a[0]), "r"(a[1]), "r"(a[2]), "r"(a[3]), "r"(b[0]), "r"(b[1]));
}

// ================ tf32x3 mma.sync GEMM: fp32 smem, in-register hi/lo split ================
// C[M,N] = A[M,K] @ B[N,K]^T + bias. CTA 128x128, 8 warps (4m x 2n), warp tile 32x64.
#define KC 16
#define ROWPAD 20
#define ARR_F (128 * ROWPAD)           // 2560 floats per operand tile
#define BUF_F (2 * ARR_F)              // A + B = 5120 floats per stage
#define GSMEM_B (2 * BUF_F * 4)        // 40960 bytes

__global__ void __launch_bounds__(256, 2)
gemm_tf32x3(const float* __restrict__ A, const float* __restrict__ B,
            const float* __restrict__ bias, float* __restrict__ C,
            int M, int N, int K)
{
    extern __shared__ __align__(128) float smem[];
    const uint32_t smb = smem_u32(smem);

    const int tid  = threadIdx.x;
    const int wid  = tid >> 5;
    const int lane = tid & 31;
    const int warp_m = wid & 3;
    const int warp_n = wid >> 2;
    const int m0 = blockIdx.y * 128;
    const int n0 = blockIdx.x * 128;

    const float* gsrc[2] = { A, B };

    float acc[2][8][4];
#pragma unroll
    for (int mt = 0; mt < 2; mt++)
#pragma unroll
        for (int nt = 0; nt < 8; nt++)
#pragma unroll
            for (int r = 0; r < 4; r++) acc[mt][nt][r] = 0.f;

    const int NCHUNK = K / KC;

    auto load_chunk = [&](int c, int buf) {
#pragma unroll
        for (int i = 0; i < 4; i++) {
            const int arr = i >> 1;
            const int f4  = (i & 1) * 256 + tid;   // 0..511 within array
            const int row = f4 >> 2;
            const int seg = f4 & 3;
            const int base = arr ? n0 : m0;
            const float* src = gsrc[arr] + (size_t)(base + row) * K + c * KC + seg * 4;
            uint32_t dst = smb + (uint32_t)(buf * BUF_F + arr * ARR_F + row * ROWPAD + seg * 4) * 4;
            CP_ASYNC16(dst, src);
        }
    };

    load_chunk(0, 0);
    CP_COMMIT();

    for (int c = 0; c < NCHUNK; c++) {
        const int buf = c & 1;
        CP_WAIT0();
        __syncthreads();
        if (c + 1 < NCHUNK) { load_chunk(c + 1, buf ^ 1); CP_COMMIT(); }

        const float* sA = smem + buf * BUF_F;
        const float* sB = sA + ARR_F;

#pragma unroll
        for (int ks = 0; ks < 2; ks++) {
            const int kb = ks * 8;
            uint32_t ah[2][4], al[2][4], bh[8][2], bl[8][2];
#pragma unroll
            for (int mt = 0; mt < 2; mt++) {
                int r = warp_m * 32 + mt * 16 + (lane >> 2);
                int cc = kb + (lane & 3);
                float r0 = sA[r * ROWPAD + cc];
                float r1 = sA[(r + 8) * ROWPAD + cc];
                float r2 = sA[r * ROWPAD + cc + 4];
                float r3 = sA[(r + 8) * ROWPAD + cc + 4];
                float h0 = tf32_rn(r0), h1 = tf32_rn(r1), h2 = tf32_rn(r2), h3 = tf32_rn(r3);
                ah[mt][0] = __float_as_uint(h0); al[mt][0] = __float_as_uint(tf32_rn(r0 - h0));
                ah[mt][1] = __float_as_uint(h1); al[mt][1] = __float_as_uint(tf32_rn(r1 - h1));
                ah[mt][2] = __float_as_uint(h2); al[mt][2] = __float_as_uint(tf32_rn(r2 - h2));
                ah[mt][3] = __float_as_uint(h3); al[mt][3] = __float_as_uint(tf32_rn(r3 - h3));
            }
#pragma unroll
            for (int nt = 0; nt < 8; nt++) {
                int nn = warp_n * 64 + nt * 8 + (lane >> 2);
                int kk = kb + (lane & 3);
                float r0 = sB[nn * ROWPAD + kk];
                float r1 = sB[nn * ROWPAD + kk + 4];
                float h0 = tf32_rn(r0), h1 = tf32_rn(r1);
                bh[nt][0] = __float_as_uint(h0); bl[nt][0] = __float_as_uint(tf32_rn(r0 - h0));
                bh[nt][1] = __float_as_uint(h1); bl[nt][1] = __float_as_uint(tf32_rn(r1 - h1));
            }
#pragma unroll
            for (int nt = 0; nt < 8; nt++)
#pragma unroll
                for (int mt = 0; mt < 2; mt++)
                    mma_tf32(acc[mt][nt], ah[mt], bh[nt]);
#pragma unroll
            for (int nt = 0; nt < 8; nt++)
#pragma unroll
                for (int mt = 0; mt < 2; mt++)
                    mma_tf32(acc[mt][nt], al[mt], bh[nt]);
#pragma unroll
            for (int nt = 0; nt < 8; nt++)
#pragma unroll
                for (int mt = 0; mt < 2; mt++)
                    mma_tf32(acc[mt][nt], ah[mt], bl[nt]);
        }
    }

#pragma unroll
    for (int mt = 0; mt < 2; mt++) {
        int r0 = m0 + warp_m * 32 + mt * 16 + (lane >> 2);
#pragma unroll
        for (int nt = 0; nt < 8; nt++) {
            int col = n0 + warp_n * 64 + nt * 8 + (lane & 3) * 2;
            float b0 = __ldg(&bias[col]);
            float b1 = __ldg(&bias[col + 1]);
            float2 v0 = { acc[mt][nt][0] + b0, acc[mt][nt][1] + b1 };
            float2 v1 = { acc[mt][nt][2] + b0, acc[mt][nt][3] + b1 };
            *reinterpret_cast<float2*>(&C[(size_t)r0 * N + col])       = v0;
            *reinterpret_cast<float2*>(&C[(size_t)(r0 + 8) * N + col]) = v1;
        }
    }
}

// ---------------- RoPE + head split + tf32 split + permuted layouts ----------------
__global__ void rope_split2(const float* __restrict__ qkv,
                            float* __restrict__ qhi, float* __restrict__ qlo,
                            float* __restrict__ khi, float* __restrict__ vthi)
{
    int idx = blockIdx.x * blockDim.x + threadIdx.x;
    const int TOT = BATCH * SEQ * NHEAD * (HDIM / 2);
    if (idx >= TOT) return;
    int i = idx % (HDIM / 2);
    int h = (idx / (HDIM / 2)) % NHEAD;
    int s = (idx / (HDIM / 2 * NHEAD)) % SEQ;
    int b = idx / (HDIM / 2 * NHEAD * SEQ);

    const float* row = qkv + (size_t)(b * SEQ + s) * (3 * DMODEL);
    int d0 = h * HDIM + 2 * i;
    float q1 = row[d0],            q2 = row[d0 + 1];
    float k1 = row[DMODEL + d0],   k2 = row[DMODEL + d0 + 1];
    float v1 = row[2*DMODEL + d0], v2 = row[2*DMODEL + d0 + 1];

    float freq = (float)pow(10000.0, -(double)(2 * i) / (double)HDIM);
    float th = (float)s * freq;
    float c  = (float)cos((double)th);
    float sn = (float)sin((double)th);

    float qa = q1 * c - q2 * sn;
    float qb = q1 * sn + q2 * c;
    float ka = k1 * c - k2 * sn;
    float kb = k1 * sn + k2 * c;

    size_t rowQ = ((size_t)((b * NHEAD + h) * SEQ + s)) * HDIM;
    int pc0 = perm8(2 * i), pc1 = perm8(2 * i + 1);
    float hh;
    // Q: d-cols permuted, hi/lo split
    hh = tf32_rn(qa); qhi[rowQ + pc0] = hh; qlo[rowQ + pc0] = tf32_rn(qa - hh);
    hh = tf32_rn(qb); qhi[rowQ + pc1] = hh; qlo[rowQ + pc1] = tf32_rn(qb - hh);
    // K: d-cols permuted, tf32-rounded (hi only)
    khi[rowQ + pc0] = tf32_rn(ka);
    khi[rowQ + pc1] = tf32_rn(kb);
    // V^T: (b,h,d,s), s-cols permuted, tf32-rounded (hi only)
    int ps = perm8(s & 7) | (s & ~7);
    size_t ov = ((size_t)((b * NHEAD + h) * HDIM + 2 * i)) * SEQ + ps;
    vthi[ov]       = tf32_rn(v1);
    vthi[ov + SEQ] = tf32_rn(v2);
}

// ---------------- tensor-core causal flash attention ----------------
// Br=128 (8 warps x 16 rows), Bc=32, Q (hi+lo) staged in SMEM once per CTA,
// K/V double-buffered via cp.async. S = (Qh+Ql)*Kh(tf32); PV = (Ph+Pl)*Vh(tf32).
#define ABC 32
#define KSTR 72
#define VSTR 40
#define KARR (ABC * KSTR)            // 2304 floats
#define VARR (HDIM * VSTR)           // 2560 floats
#define ASTAGE (KARR + VARR)         // 4864 floats
#define QARR (128 * KSTR)            // 9216 floats
#define ASMEM_B ((2 * QARR + 2 * ASTAGE) * 4)   // 112640 bytes

__global__ void __launch_bounds__(256, 2)
attn_mma(const float* __restrict__ Qh, const float* __restrict__ Ql,
         const float* __restrict__ Khg, const float* __restrict__ Vhg,
         float* __restrict__ Og)
{
    extern __shared__ __align__(128) float sm[];
    const uint32_t smb = smem_u32(sm);

    const int tid  = threadIdx.x;
    const int w    = tid >> 5;
    const int lane = tid & 31;
    const int g    = lane >> 2;
    const int q    = lane & 3;

    const int qblk = gridDim.x - 1 - blockIdx.x;   // heavy CTAs first
    const int h    = blockIdx.y;
    const int b    = blockIdx.z;
    const int qbase = qblk * 128 + 16 * w;

    const size_t headQK = (size_t)(b * NHEAD + h) * SEQ * HDIM;
    const size_t headV  = (size_t)(b * NHEAD + h) * HDIM * SEQ;

    // ---- Q tile (hi+lo) -> smem, async ----
    {
        const float* qsrc[2] = { Qh + headQK + (size_t)qblk * 128 * 64,
                                 Ql + headQK + (size_t)qblk * 128 * 64 };
#pragma unroll
        for (int arr = 0; arr < 2; arr++) {
#pragma unroll
            for (int i = 0; i < 8; i++) {
                int idx = i * 256 + tid;          // 0..2047 float4
                int row = idx >> 4;
                int c4  = (idx & 15) * 4;
                uint32_t dst = smb + (uint32_t)(arr * QARR + row * KSTR + c4) * 4;
                CP_ASYNC16(dst, qsrc[arr] + (size_t)row * 64 + c4);
            }
        }
    }

    auto load_tile = [&](int t, int stg) {
        const int n0t = t * ABC;
        const uint32_t sb = smb + (uint32_t)(2 * QARR + stg * ASTAGE) * 4;
        // Kh: 32 rows x 64 cols
#pragma unroll
        for (int i = 0; i < 2; i++) {
            int idx = i * 256 + tid;              // 0..511
            int row = idx >> 4;
            int c4  = (idx & 15) * 4;
            CP_ASYNC16(sb + (uint32_t)(row * KSTR + c4) * 4,
                       Khg + headQK + (size_t)(n0t + row) * 64 + c4);
        }
        // Vh^T: 64 d-rows x 32 s-cols
#pragma unroll
        for (int i = 0; i < 2; i++) {
            int idx = i * 256 + tid;              // 0..511
            int row = idx >> 3;
            int c4  = (idx & 7) * 4;
            CP_ASYNC16(sb + (uint32_t)(KARR + row * VSTR + c4) * 4,
                       Vhg + headV + (size_t)row * SEQ + n0t + c4);
        }
    };

    load_tile(0, 0);
    CP_COMMIT();      // group 0 = Q + tile 0

    float o[8][4];
#pragma unroll
    for (int j = 0; j < 8; j++)
#pragma unroll
        for (int e = 0; e < 4; e++) o[j][e] = 0.f;
    float mrow0 = -INFINITY, mrow1 = -INFINITY;
    float lrow0 = 0.f, lrow1 = 0.f;

    const float sscale = 0.125f * 1.44269504088896340736f;
    const int ntiles = 4 * (qblk + 1);
    const int r0 = 16 * w + g;

    for (int t = 0; t < ntiles; t++) {
        const int stg = t & 1;
        const int n0 = t * ABC;

        if (t + 1 < ntiles) {
            load_tile(t + 1, stg ^ 1);
            CP_COMMIT();
            CP_WAIT1();
        } else {
            CP_WAIT0();
        }
        __syncthreads();

        if (n0 <= qbase + 15) {
            const float* sQh = sm;
            const float* sQl = sm + QARR;
            const float* sKh = sm + 2 * QARR + stg * ASTAGE;
            const float* sVh = sKh + KARR;

            // ---- S = Q K^T ----
            float acc[4][4];
#pragma unroll
            for (int j = 0; j < 4; j++)
#pragma unroll
                for (int e = 0; e < 4; e++) acc[j][e] = 0.f;

#pragma unroll
            for (int kk = 0; kk < 8; kk++) {
                float2 h0 = *reinterpret_cast<const float2*>(&sQh[r0 * KSTR + kk * 8 + 2 * q]);
                float2 h1 = *reinterpret_cast<const float2*>(&sQh[(r0 + 8) * KSTR + kk * 8 + 2 * q]);
                float2 l0 = *reinterpret_cast<const float2*>(&sQl[r0 * KSTR + kk * 8 + 2 * q]);
                float2 l1 = *reinterpret_cast<const float2*>(&sQl[(r0 + 8) * KSTR + kk * 8 + 2 * q]);
                uint32_t a_h[4] = { __float_as_uint(h0.x), __float_as_uint(h1.x),
                                    __float_as_uint(h0.y), __float_as_uint(h1.y) };
                uint32_t a_l[4] = { __float_as_uint(l0.x), __float_as_uint(l1.x),
                                    __float_as_uint(l0.y), __float_as_uint(l1.y) };
#pragma unroll
                for (int j = 0; j < 4; j++) {
                    float2 bk = *reinterpret_cast<const float2*>(
                        &sKh[(8 * j + g) * KSTR + kk * 8 + 2 * q]);
                    uint32_t ub[2] = { __float_as_uint(bk.x), __float_as_uint(bk.y) };
                    mma_tf32(acc[j], a_h, ub);
                    mma_tf32(acc[j], a_l, ub);
                }
            }

            // ---- softmax (log2 domain) ----
            const bool needmask = (n0 + 31 > qbase);
            float tmax0 = -INFINITY, tmax1 = -INFINITY;
#pragma unroll
            for (int j = 0; j < 4; j++) {
#pragma unroll
                for (int e = 0; e < 4; e++) {
                    float s = acc[j][e] * sscale;
                    if (needmask) {
                        int col = n0 + 8 * j + 2 * q + (e & 1);
                        int rw  = qbase + g + ((e >> 1) << 3);
                        if (col > rw) s = -INFINITY;
                    }
                    acc[j][e] = s;
                    if (e < 2) tmax0 = fmaxf(tmax0, s);
                    else       tmax1 = fmaxf(tmax1, s);
                }
            }
            tmax0 = fmaxf(tmax0, __shfl_xor_sync(0xffffffffu, tmax0, 1));
            tmax0 = fmaxf(tmax0, __shfl_xor_sync(0xffffffffu, tmax0, 2));
            tmax1 = fmaxf(tmax1, __shfl_xor_sync(0xffffffffu, tmax1, 1));
            tmax1 = fmaxf(tmax1, __shfl_xor_sync(0xffffffffu, tmax1, 2));

            float mn0 = fmaxf(mrow0, tmax0);
            float mn1 = fmaxf(mrow1, tmax1);
            float corr0 = ex2(mrow0 - mn0);
            float corr1 = ex2(mrow1 - mn1);

            float sum0 = 0.f, sum1 = 0.f;
#pragma unroll
            for (int j = 0; j < 4; j++) {
                float p0 = ex2(acc[j][0] - mn0);
                float p1 = ex2(acc[j][1] - mn0);
                float p2 = ex2(acc[j][2] - mn1);
                float p3 = ex2(acc[j][3] - mn1);
                acc[j][0] = p0; acc[j][1] = p1; acc[j][2] = p2; acc[j][3] = p3;
                sum0 += p0 + p1;
                sum1 += p2 + p3;
            }
            sum0 += __shfl_xor_sync(0xffffffffu, sum0, 1);
            sum0 += __shfl_xor_sync(0xffffffffu, sum0, 2);
            sum1 += __shfl_xor_sync(0xffffffffu, sum1, 1);
            sum1 += __shfl_xor_sync(0xffffffffu, sum1, 2);

            lrow0 = lrow0 * corr0 + sum0;
            lrow1 = lrow1 * corr1 + sum1;
            mrow0 = mn0;
            mrow1 = mn1;

#pragma unroll
            for (int j = 0; j < 8; j++) {
                o[j][0] *= corr0; o[j][1] *= corr0;
                o[j][2] *= corr1; o[j][3] *= corr1;
            }

            // ---- O += P V ----
            const int srcA = (lane & ~3) | (q >> 1);
            const int srcB = srcA + 2;
            const bool odd = (q & 1);
#pragma unroll
            for (int kk = 0; kk < 4; kk++) {
                float x0 = __shfl_sync(0xffffffffu, acc[kk][0], srcA);
                float x1 = __shfl_sync(0xffffffffu, acc[kk][1], srcA);
                float x2 = __shfl_sync(0xffffffffu, acc[kk][2], srcA);
                float x3 = __shfl_sync(0xffffffffu, acc[kk][3], srcA);
                float y0 = __shfl_sync(0xffffffffu, acc[kk][0], srcB);
                float y1 = __shfl_sync(0xffffffffu, acc[kk][1], srcB);
                float y2 = __shfl_sync(0xffffffffu, acc[kk][2], srcB);
                float y3 = __shfl_sync(0xffffffffu, acc[kk][3], srcB);
                float a0 = odd ? x1 : x0;
                float a1 = odd ? x3 : x2;
                float a2 = odd ? y1 : y0;
                float a3 = odd ? y3 : y2;

                float h0 = tf32_rn(a0), l0 = tf32_rn(a0 - h0);
                float h1 = tf32_rn(a1), l1 = tf32_rn(a1 - h1);
                float h2 = tf32_rn(a2), l2 = tf32_rn(a2 - h2);
                float h3 = tf32_rn(a3), l3 = tf32_rn(a3 - h3);
                uint32_t uph[4] = { __float_as_uint(h0), __float_as_uint(h1),
                                    __float_as_uint(h2), __float_as_uint(h3) };
                uint32_t upl[4] = { __float_as_uint(l0), __float_as_uint(l1),
                                    __float_as_uint(l2), __float_as_uint(l3) };
#pragma unroll
                for (int j2 = 0; j2 < 8; j2++) {
                    float2 vh = *reinterpret_cast<const float2*>(
                        &sVh[(8 * j2 + g) * VSTR + kk * 8 + 2 * q]);
                    uint32_t uvh[2] = { __float_as_uint(vh.x), __float_as_uint(vh.y) };
                    mma_tf32(o[j2], uph, uvh);
                    mma_tf32(o[j2], upl, uvh);
                }
            }
        }
        __syncthreads();
    }

    // ---- epilogue ----
    float inv0 = 1.f / lrow0;
    float inv1 = 1.f / lrow1;
    float* ob = Og + ((size_t)(b * SEQ + qbase + g)) * DMODEL + h * HDIM;
#pragma unroll
    for (int j2 = 0; j2 < 8; j2++) {
        int d0 = 8 * j2 + 2 * q;
        float2 v0 = { o[j2][0] * inv0, o[j2][1] * inv0 };
        float2 v1 = { o[j2][2] * inv1, o[j2][3] * inv1 };
        *reinterpret_cast<float2*>(&ob[d0]) = v0;
        *reinterpret_cast<float2*>(&ob[(size_t)8 * DMODEL + d0]) = v1;
    }
}

// ---------------- launcher ----------------
extern "C" void kernel_launch(void* const* d_in, const int* in_sizes, int n_in,
                              void* d_out, int out_size)
{
    const float* x     = (const float*)d_in[0];
    const float* w_qkv = (const float*)d_in[1];
    const float* b_qkv = (const float*)d_in[2];
    const float* w_out = (const float*)d_in[3];
    const float* b_out = (const float*)d_in[4];
    float* out = (float*)d_out;

    float *qkv, *att, *qhi, *qlo, *khi, *vth;
    cudaGetSymbolAddress((void**)&qkv, g_qkv);
    cudaGetSymbolAddress((void**)&att, g_att);
    cudaGetSymbolAddress((void**)&qhi, g_qhi);
    cudaGetSymbolAddress((void**)&qlo, g_qlo);
    cudaGetSymbolAddress((void**)&khi, g_khi);
    cudaGetSymbolAddress((void**)&vth, g_vthi);

    cudaFuncSetAttribute(gemm_tf32x3,
                         cudaFuncAttributeMaxDynamicSharedMemorySize, GSMEM_B);
    cudaFuncSetAttribute(attn_mma,
                         cudaFuncAttributeMaxDynamicSharedMemorySize, ASMEM_B);

    // 1) QKV projection (reads x / w_qkv directly, in-register tf32 split)
    {
        dim3 grid(3 * DMODEL / 128, MROWS / 128);
        gemm_tf32x3<<<grid, 256, GSMEM_B>>>(x, w_qkv, b_qkv, qkv,
                                            MROWS, 3 * DMODEL, DMODEL);
    }
    // 2) RoPE + head split + tf32 split + permuted layouts
    {
        int tot = BATCH * SEQ * NHEAD * (HDIM / 2);
        rope_split2<<<(tot + 255) / 256, 256>>>(qkv, qhi, qlo, khi, vth);
    }
    // 3) tensor-core causal attention
    {
        dim3 grid(SEQ / 128, NHEAD, BATCH);
        attn_mma<<<grid, 256, ASMEM_B>>>(qhi, qlo, khi, vth, att);
    }
    // 4) output projection
    {
        dim3 grid(DMODEL / 128, MROWS / 128);
        gemm_tf32x3<<<grid, 256, GSMEM_B>>>(att, w_out, b_out, out,
                                            MROWS, DMODEL, DMODEL);
    }
}

// round 9
// speedup vs baseline: 2.6261x; 1.3657x over previous
#include <cuda_runtime.h>
#include <cuda_bf16.h>
#include <cstdint>
#include <math.h>

// Problem constants
#define BATCH 2
#define SEQ   2048
#define DMODEL 1024
#define NHEAD 16
#define HDIM  64
#define MROWS (BATCH*SEQ)          // 4096

// ---------------- scratch (no cudaMalloc allowed) ----------------
__device__ float g_qkv[MROWS * 3 * DMODEL];                 // (B*S, 3072)
__device__ float g_att[MROWS * DMODEL];                     // (B*S, 1024)

// attention operands (tf32-domain)
#define HELEMS (BATCH * NHEAD * SEQ * HDIM)
__device__ float g_qhi[HELEMS], g_qlo[HELEMS];   // (b,h,s,d) d-cols perm8'd
__device__ float g_khi[HELEMS];                  // (b,h,s,d) d-cols perm8'd
__device__ float g_vthi[HELEMS];                 // (b,h,d,s) natural s order

// ================= helpers =================
__device__ __forceinline__ uint32_t smem_u32(const void* p) {
    uint32_t a;
    asm("{ .reg .u64 t; cvta.to.shared.u64 t, %1; cvt.u32.u64 %0, t; }" : "=r"(a) : "l"(p));
    return a;
}
__device__ __forceinline__ float tf32_rn(float x) {
    uint32_t u;
    asm("cvt.rna.tf32.f32 %0, %1;" : "=r"(u) : "f"(x));
    return __uint_as_float(u);
}
__device__ __forceinline__ float ex2(float x) {
    float y;
    asm("ex2.approx.f32 %0, %1;" : "=f"(y) : "f"(x));
    return y;
}
__device__ __forceinline__ int perm8(int c) {
    return (c & ~7) | ((c & 3) << 1) | ((c >> 2) & 1);
}
#define CP_ASYNC16(dst, src) \
    asm volatile("cp.async.cg.shared.global [%0], [%1], 16;" :: "r"(dst), "l"(src))
#define CP_COMMIT() asm volatile("cp.async.commit_group;" ::: "memory")
#define CP_WAIT0()  asm volatile("cp.async.wait_group 0;" ::: "memory")
#define CP_WAIT1()  asm volatile("cp.async.wait_group 1;" ::: "memory")

__device__ __forceinline__ void mma_tf32(float* d, const uint32_t* a, const uint32_t* b) {
    asm volatile(
        "mma.sync.aligned.m16n8k8.row.col.f32.tf32.tf32.f32 "
        "{%0,%1,%2,%3}, {%4,%5,%6,%7}, {%8,%9}, {%0,%1,%2,%3};"
        : "+f"(d[0]), "+f"(d[1]), "+f"(d[2]), "+f"(d[3])
        : "r"(a[0]), "r"(a[1]), "r"(a[2]), "r"(a[3]), "r"(b[0]), "r"(b[1]));
}

// ================ tf32x3 mma.sync GEMM: fp32 smem, in-register hi/lo split ================
#define KC 16
#define ROWPAD 20
#define ARR_F (128 * ROWPAD)
#define BUF_F (2 * ARR_F)
#define GSMEM_B (2 * BUF_F * 4)        // 40960 bytes

__global__ void __launch_bounds__(256, 2)
gemm_tf32x3(const float* __restrict__ A, const float* __restrict__ B,
            const float* __restrict__ bias, float* __restrict__ C,
            int M, int N, int K)
{
    extern __shared__ __align__(128) float smem[];
    const uint32_t smb = smem_u32(smem);

    const int tid  = threadIdx.x;
    const int wid  = tid >> 5;
    const int lane = tid & 31;
    const int warp_m = wid & 3;
    const int warp_n = wid >> 2;
    const int m0 = blockIdx.y * 128;
    const int n0 = blockIdx.x * 128;

    const float* gsrc[2] = { A, B };

    float acc[2][8][4];
#pragma unroll
    for (int mt = 0; mt < 2; mt++)
#pragma unroll
        for (int nt = 0; nt < 8; nt++)
#pragma unroll
            for (int r = 0; r < 4; r++) acc[mt][nt][r] = 0.f;

    const int NCHUNK = K / KC;

    auto load_chunk = [&](int c, int buf) {
#pragma unroll
        for (int i = 0; i < 4; i++) {
            const int arr = i >> 1;
            const int f4  = (i & 1) * 256 + tid;
            const int row = f4 >> 2;
            const int seg = f4 & 3;
            const int base = arr ? n0 : m0;
            const float* src = gsrc[arr] + (size_t)(base + row) * K + c * KC + seg * 4;
            uint32_t dst = smb + (uint32_t)(buf * BUF_F + arr * ARR_F + row * ROWPAD + seg * 4) * 4;
            CP_ASYNC16(dst, src);
        }
    };

    load_chunk(0, 0);
    CP_COMMIT();

    for (int c = 0; c < NCHUNK; c++) {
        const int buf = c & 1;
        CP_WAIT0();
        __syncthreads();
        if (c + 1 < NCHUNK) { load_chunk(c + 1, buf ^ 1); CP_COMMIT(); }

        const float* sA = smem + buf * BUF_F;
        const float* sB = sA + ARR_F;

#pragma unroll
        for (int ks = 0; ks < 2; ks++) {
            const int kb = ks * 8;
            uint32_t ah[2][4], al[2][4], bh[8][2], bl[8][2];
#pragma unroll
            for (int mt = 0; mt < 2; mt++) {
                int r = warp_m * 32 + mt * 16 + (lane >> 2);
                int cc = kb + (lane & 3);
                float r0 = sA[r * ROWPAD + cc];
                float r1 = sA[(r + 8) * ROWPAD + cc];
                float r2 = sA[r * ROWPAD + cc + 4];
                float r3 = sA[(r + 8) * ROWPAD + cc + 4];
                float h0 = tf32_rn(r0), h1 = tf32_rn(r1), h2 = tf32_rn(r2), h3 = tf32_rn(r3);
                ah[mt][0] = __float_as_uint(h0); al[mt][0] = __float_as_uint(tf32_rn(r0 - h0));
                ah[mt][1] = __float_as_uint(h1); al[mt][1] = __float_as_uint(tf32_rn(r1 - h1));
                ah[mt][2] = __float_as_uint(h2); al[mt][2] = __float_as_uint(tf32_rn(r2 - h2));
                ah[mt][3] = __float_as_uint(h3); al[mt][3] = __float_as_uint(tf32_rn(r3 - h3));
            }
#pragma unroll
            for (int nt = 0; nt < 8; nt++) {
                int nn = warp_n * 64 + nt * 8 + (lane >> 2);
                int kk = kb + (lane & 3);
                float r0 = sB[nn * ROWPAD + kk];
                float r1 = sB[nn * ROWPAD + kk + 4];
                float h0 = tf32_rn(r0), h1 = tf32_rn(r1);
                bh[nt][0] = __float_as_uint(h0); bl[nt][0] = __float_as_uint(tf32_rn(r0 - h0));
                bh[nt][1] = __float_as_uint(h1); bl[nt][1] = __float_as_uint(tf32_rn(r1 - h1));
            }
#pragma unroll
            for (int nt = 0; nt < 8; nt++)
#pragma unroll
                for (int mt = 0; mt < 2; mt++)
                    mma_tf32(acc[mt][nt], ah[mt], bh[nt]);
#pragma unroll
            for (int nt = 0; nt < 8; nt++)
#pragma unroll
                for (int mt = 0; mt < 2; mt++)
                    mma_tf32(acc[mt][nt], al[mt], bh[nt]);
#pragma unroll
            for (int nt = 0; nt < 8; nt++)
#pragma unroll
                for (int mt = 0; mt < 2; mt++)
                    mma_tf32(acc[mt][nt], ah[mt], bl[nt]);
        }
    }

#pragma unroll
    for (int mt = 0; mt < 2; mt++) {
        int r0 = m0 + warp_m * 32 + mt * 16 + (lane >> 2);
#pragma unroll
        for (int nt = 0; nt < 8; nt++) {
            int col = n0 + warp_n * 64 + nt * 8 + (lane & 3) * 2;
            float b0 = __ldg(&bias[col]);
            float b1 = __ldg(&bias[col + 1]);
            float2 v0 = { acc[mt][nt][0] + b0, acc[mt][nt][1] + b1 };
            float2 v1 = { acc[mt][nt][2] + b0, acc[mt][nt][3] + b1 };
            *reinterpret_cast<float2*>(&C[(size_t)r0 * N + col])       = v0;
            *reinterpret_cast<float2*>(&C[(size_t)(r0 + 8) * N + col]) = v1;
        }
    }
}

// ---------------- RoPE + head split + tf32 split + layouts ----------------
__global__ void rope_split2(const float* __restrict__ qkv,
                            float* __restrict__ qhi, float* __restrict__ qlo,
                            float* __restrict__ khi, float* __restrict__ vthi)
{
    int idx = blockIdx.x * blockDim.x + threadIdx.x;
    const int TOT = BATCH * SEQ * NHEAD * (HDIM / 2);
    if (idx >= TOT) return;
    int i = idx % (HDIM / 2);
    int h = (idx / (HDIM / 2)) % NHEAD;
    int s = (idx / (HDIM / 2 * NHEAD)) % SEQ;
    int b = idx / (HDIM / 2 * NHEAD * SEQ);

    const float* row = qkv + (size_t)(b * SEQ + s) * (3 * DMODEL);
    int d0 = h * HDIM + 2 * i;
    float q1 = row[d0],            q2 = row[d0 + 1];
    float k1 = row[DMODEL + d0],   k2 = row[DMODEL + d0 + 1];
    float v1 = row[2*DMODEL + d0], v2 = row[2*DMODEL + d0 + 1];

    // freq bit-exact via double exp2 (matches reference's f32 freq), fp32 trig.
    float freq = (float)exp2(-(double)(2 * i) * 0.21457191214273827);  // log2(1e4)/64... see note
    // NOTE: log2(10000)/64 = 13.28771237954945/64 = 0.2076205059304601
    freq = (float)exp2(-(double)(2 * i) * 0.2076205059304601);
    float th = (float)s * freq;
    float c, sn;
    sincosf(th, &sn, &c);

    float qa = q1 * c - q2 * sn;
    float qb = q1 * sn + q2 * c;
    float ka = k1 * c - k2 * sn;
    float kb = k1 * sn + k2 * c;

    size_t rowQ = ((size_t)((b * NHEAD + h) * SEQ + s)) * HDIM;
    int pc0 = perm8(2 * i), pc1 = perm8(2 * i + 1);
    float hh;
    hh = tf32_rn(qa); qhi[rowQ + pc0] = hh; qlo[rowQ + pc0] = tf32_rn(qa - hh);
    hh = tf32_rn(qb); qhi[rowQ + pc1] = hh; qlo[rowQ + pc1] = tf32_rn(qb - hh);
    khi[rowQ + pc0] = tf32_rn(ka);
    khi[rowQ + pc1] = tf32_rn(kb);
    // V^T: (b,h,d,s), natural s order
    size_t ov = ((size_t)((b * NHEAD + h) * HDIM + 2 * i)) * SEQ + s;
    vthi[ov]       = tf32_rn(v1);
    vthi[ov + SEQ] = tf32_rn(v2);
}

// ---------------- tensor-core causal flash attention ----------------
#define ABC 32
#define KSTR 72
#define VSTR 40
#define KARR (ABC * KSTR)            // 2304 floats
#define VARR (HDIM * VSTR)           // 2560 floats
#define ASTAGE (KARR + VARR)         // 4864 floats
#define QARR (128 * KSTR)            // 9216 floats
#define ASMEM_B ((2 * QARR + 2 * ASTAGE) * 4)   // 112640 bytes

__global__ void __launch_bounds__(256, 2)
attn_mma(const float* __restrict__ Qh, const float* __restrict__ Ql,
         const float* __restrict__ Khg, const float* __restrict__ Vhg,
         float* __restrict__ Og)
{
    extern __shared__ __align__(128) float sm[];
    const uint32_t smb = smem_u32(sm);

    const int tid  = threadIdx.x;
    const int w    = tid >> 5;
    const int lane = tid & 31;
    const int g    = lane >> 2;
    const int q    = lane & 3;

    const int qblk = gridDim.x - 1 - blockIdx.x;
    const int h    = blockIdx.y;
    const int b    = blockIdx.z;
    const int qbase = qblk * 128 + 16 * w;

    const size_t headQK = (size_t)(b * NHEAD + h) * SEQ * HDIM;
    const size_t headV  = (size_t)(b * NHEAD + h) * HDIM * SEQ;

    // ---- Q tile (hi+lo) -> smem, async ----
    {
        const float* qsrc[2] = { Qh + headQK + (size_t)qblk * 128 * 64,
                                 Ql + headQK + (size_t)qblk * 128 * 64 };
#pragma unroll
        for (int arr = 0; arr < 2; arr++) {
#pragma unroll
            for (int i = 0; i < 8; i++) {
                int idx = i * 256 + tid;
                int row = idx >> 4;
                int c4  = (idx & 15) * 4;
                uint32_t dst = smb + (uint32_t)(arr * QARR + row * KSTR + c4) * 4;
                CP_ASYNC16(dst, qsrc[arr] + (size_t)row * 64 + c4);
            }
        }
    }

    auto load_tile = [&](int t, int stg) {
        const int n0t = t * ABC;
        const uint32_t sb = smb + (uint32_t)(2 * QARR + stg * ASTAGE) * 4;
#pragma unroll
        for (int i = 0; i < 2; i++) {
            int idx = i * 256 + tid;
            int row = idx >> 4;
            int c4  = (idx & 15) * 4;
            CP_ASYNC16(sb + (uint32_t)(row * KSTR + c4) * 4,
                       Khg + headQK + (size_t)(n0t + row) * 64 + c4);
        }
#pragma unroll
        for (int i = 0; i < 2; i++) {
            int idx = i * 256 + tid;
            int row = idx >> 3;
            int c4  = (idx & 7) * 4;
            CP_ASYNC16(sb + (uint32_t)(KARR + row * VSTR + c4) * 4,
                       Vhg + headV + (size_t)row * SEQ + n0t + c4);
        }
    };

    load_tile(0, 0);
    CP_COMMIT();

    float o[8][4];
#pragma unroll
    for (int j = 0; j < 8; j++)
#pragma unroll
        for (int e = 0; e < 4; e++) o[j][e] = 0.f;
    float mrow0 = -INFINITY, mrow1 = -INFINITY;
    float lrow0 = 0.f, lrow1 = 0.f;

    const float sscale = 0.125f * 1.44269504088896340736f;
    const int ntiles = 4 * (qblk + 1);
    const int r0 = 16 * w + g;

    for (int t = 0; t < ntiles; t++) {
        const int stg = t & 1;
        const int n0 = t * ABC;

        if (t + 1 < ntiles) {
            load_tile(t + 1, stg ^ 1);
            CP_COMMIT();
            CP_WAIT1();
        } else {
            CP_WAIT0();
        }
        __syncthreads();

        if (n0 <= qbase + 15) {
            const float* sQh = sm;
            const float* sQl = sm + QARR;
            const float* sKh = sm + 2 * QARR + stg * ASTAGE;
            const float* sVh = sKh + KARR;

            // ---- S = Q K^T : separate hi/lo accumulators (RAW distance 8) ----
            float acc_h[4][4], acc_l[4][4];
#pragma unroll
            for (int j = 0; j < 4; j++)
#pragma unroll
                for (int e = 0; e < 4; e++) { acc_h[j][e] = 0.f; acc_l[j][e] = 0.f; }

#pragma unroll
            for (int kk = 0; kk < 8; kk++) {
                float2 h0 = *reinterpret_cast<const float2*>(&sQh[r0 * KSTR + kk * 8 + 2 * q]);
                float2 h1 = *reinterpret_cast<const float2*>(&sQh[(r0 + 8) * KSTR + kk * 8 + 2 * q]);
                float2 l0 = *reinterpret_cast<const float2*>(&sQl[r0 * KSTR + kk * 8 + 2 * q]);
                float2 l1 = *reinterpret_cast<const float2*>(&sQl[(r0 + 8) * KSTR + kk * 8 + 2 * q]);
                uint32_t a_h[4] = { __float_as_uint(h0.x), __float_as_uint(h1.x),
                                    __float_as_uint(h0.y), __float_as_uint(h1.y) };
                uint32_t a_l[4] = { __float_as_uint(l0.x), __float_as_uint(l1.x),
                                    __float_as_uint(l0.y), __float_as_uint(l1.y) };
                uint32_t ub[4][2];
#pragma unroll
                for (int j = 0; j < 4; j++) {
                    float2 bk = *reinterpret_cast<const float2*>(
                        &sKh[(8 * j + g) * KSTR + kk * 8 + 2 * q]);
                    ub[j][0] = __float_as_uint(bk.x);
                    ub[j][1] = __float_as_uint(bk.y);
                }
#pragma unroll
                for (int j = 0; j < 4; j++) mma_tf32(acc_h[j], a_h, ub[j]);
#pragma unroll
                for (int j = 0; j < 4; j++) mma_tf32(acc_l[j], a_l, ub[j]);
            }

            float acc[4][4];
#pragma unroll
            for (int j = 0; j < 4; j++)
#pragma unroll
                for (int e = 0; e < 4; e++) acc[j][e] = acc_h[j][e] + acc_l[j][e];

            // ---- softmax (log2 domain) ----
            const bool needmask = (n0 + 31 > qbase);
            float tmax0 = -INFINITY, tmax1 = -INFINITY;
#pragma unroll
            for (int j = 0; j < 4; j++) {
#pragma unroll
                for (int e = 0; e < 4; e++) {
                    float s = acc[j][e] * sscale;
                    if (needmask) {
                        int col = n0 + 8 * j + 2 * q + (e & 1);
                        int rw  = qbase + g + ((e >> 1) << 3);
                        if (col > rw) s = -INFINITY;
                    }
                    acc[j][e] = s;
                    if (e < 2) tmax0 = fmaxf(tmax0, s);
                    else       tmax1 = fmaxf(tmax1, s);
                }
            }
            tmax0 = fmaxf(tmax0, __shfl_xor_sync(0xffffffffu, tmax0, 1));
            tmax0 = fmaxf(tmax0, __shfl_xor_sync(0xffffffffu, tmax0, 2));
            tmax1 = fmaxf(tmax1, __shfl_xor_sync(0xffffffffu, tmax1, 1));
            tmax1 = fmaxf(tmax1, __shfl_xor_sync(0xffffffffu, tmax1, 2));

            float mn0 = fmaxf(mrow0, tmax0);
            float mn1 = fmaxf(mrow1, tmax1);
            float corr0 = ex2(mrow0 - mn0);
            float corr1 = ex2(mrow1 - mn1);

            float sum0 = 0.f, sum1 = 0.f;
#pragma unroll
            for (int j = 0; j < 4; j++) {
                float p0 = ex2(acc[j][0] - mn0);
                float p1 = ex2(acc[j][1] - mn0);
                float p2 = ex2(acc[j][2] - mn1);
                float p3 = ex2(acc[j][3] - mn1);
                acc[j][0] = p0; acc[j][1] = p1; acc[j][2] = p2; acc[j][3] = p3;
                sum0 += p0 + p1;
                sum1 += p2 + p3;
            }
            sum0 += __shfl_xor_sync(0xffffffffu, sum0, 1);
            sum0 += __shfl_xor_sync(0xffffffffu, sum0, 2);
            sum1 += __shfl_xor_sync(0xffffffffu, sum1, 1);
            sum1 += __shfl_xor_sync(0xffffffffu, sum1, 2);

            lrow0 = lrow0 * corr0 + sum0;
            lrow1 = lrow1 * corr1 + sum1;
            mrow0 = mn0;
            mrow1 = mn1;

#pragma unroll
            for (int j = 0; j < 8; j++) {
                o[j][0] *= corr0; o[j][1] *= corr0;
                o[j][2] *= corr1; o[j][3] *= corr1;
            }

            // ---- O += P V : acc IS the A-fragment (slot relabel), no shuffles ----
#pragma unroll
            for (int kk = 0; kk < 4; kk++) {
                float p0 = acc[kk][0], p1 = acc[kk][1];
                float p2 = acc[kk][2], p3 = acc[kk][3];
                float h0 = tf32_rn(p0), l0v = tf32_rn(p0 - h0);
                float h1 = tf32_rn(p2), l1v = tf32_rn(p2 - h1);
                float h2 = tf32_rn(p1), l2v = tf32_rn(p1 - h2);
                float h3 = tf32_rn(p3), l3v = tf32_rn(p3 - h3);
                uint32_t uph[4] = { __float_as_uint(h0), __float_as_uint(h1),
                                    __float_as_uint(h2), __float_as_uint(h3) };
                uint32_t upl[4] = { __float_as_uint(l0v), __float_as_uint(l1v),
                                    __float_as_uint(l2v), __float_as_uint(l3v) };
#pragma unroll
                for (int j2 = 0; j2 < 8; j2++) {
                    float2 vh = *reinterpret_cast<const float2*>(
                        &sVh[(8 * j2 + g) * VSTR + kk * 8 + 2 * q]);
                    uint32_t uvh[2] = { __float_as_uint(vh.x), __float_as_uint(vh.y) };
                    mma_tf32(o[j2], uph, uvh);
                }
#pragma unroll
                for (int j2 = 0; j2 < 8; j2++) {
                    float2 vh = *reinterpret_cast<const float2*>(
                        &sVh[(8 * j2 + g) * VSTR + kk * 8 + 2 * q]);
                    uint32_t uvh[2] = { __float_as_uint(vh.x), __float_as_uint(vh.y) };
                    mma_tf32(o[j2], upl, uvh);
                }
            }
        }
        __syncthreads();
    }

    // ---- epilogue ----
    float inv0 = 1.f / lrow0;
    float inv1 = 1.f / lrow1;
    float* ob = Og + ((size_t)(b * SEQ + qbase + g)) * DMODEL + h * HDIM;
#pragma unroll
    for (int j2 = 0; j2 < 8; j2++) {
        int d0 = 8 * j2 + 2 * q;
        float2 v0 = { o[j2][0] * inv0, o[j2][1] * inv0 };
        float2 v1 = { o[j2][2] * inv1, o[j2][3] * inv1 };
        *reinterpret_cast<float2*>(&ob[d0]) = v0;
        *reinterpret_cast<float2*>(&ob[(size_t)8 * DMODEL + d0]) = v1;
    }
}

// ---------------- launcher ----------------
extern "C" void kernel_launch(void* const* d_in, const int* in_sizes, int n_in,
                              void* d_out, int out_size)
{
    const float* x     = (const float*)d_in[0];
    const float* w_qkv = (const float*)d_in[1];
    const float* b_qkv = (const float*)d_in[2];
    const float* w_out = (const float*)d_in[3];
    const float* b_out = (const float*)d_in[4];
    float* out = (float*)d_out;

    float *qkv, *att, *qhi, *qlo, *khi, *vth;
    cudaGetSymbolAddress((void**)&qkv, g_qkv);
    cudaGetSymbolAddress((void**)&att, g_att);
    cudaGetSymbolAddress((void**)&qhi, g_qhi);
    cudaGetSymbolAddress((void**)&qlo, g_qlo);
    cudaGetSymbolAddress((void**)&khi, g_khi);
    cudaGetSymbolAddress((void**)&vth, g_vthi);

    cudaFuncSetAttribute(gemm_tf32x3,
                         cudaFuncAttributeMaxDynamicSharedMemorySize, GSMEM_B);
    cudaFuncSetAttribute(attn_mma,
                         cudaFuncAttributeMaxDynamicSharedMemorySize, ASMEM_B);

    // 1) QKV projection
    {
        dim3 grid(3 * DMODEL / 128, MROWS / 128);
        gemm_tf32x3<<<grid, 256, GSMEM_B>>>(x, w_qkv, b_qkv, qkv,
                                            MROWS, 3 * DMODEL, DMODEL);
    }
    // 2) RoPE + head split + tf32 split
    {
        int tot = BATCH * SEQ * NHEAD * (HDIM / 2);
        rope_split2<<<(tot + 255) / 256, 256>>>(qkv, qhi, qlo, khi, vth);
    }
    // 3) tensor-core causal attention
    {
        dim3 grid(SEQ / 128, NHEAD, BATCH);
        attn_mma<<<grid, 256, ASMEM_B>>>(qhi, qlo, khi, vth, att);
    }
    // 4) output projection
    {
        dim3 grid(DMODEL / 128, MROWS / 128);
        gemm_tf32x3<<<grid, 256, GSMEM_B>>>(att, w_out, b_out, out,
                                            MROWS, DMODEL, DMODEL);
    }
}